// round 8
// baseline (speedup 1.0000x reference)
#include <cuda_runtime.h>
#include <cuda_bf16.h>
#include <math.h>

typedef unsigned long long ull;

// ---------------- device scratch ----------------
__device__ float g_act0[512*32*32*32];
__device__ float g_act1[512*64*16*16];
__device__ float g_act2[512*128*16*16];
__device__ float g_feats[512*256];
__device__ float g_logits[512*8*10];
__device__ float g_conf[512*8];
__device__ int   g_D[512*8];
__device__ float g_scale[4*256];
__device__ float g_bias[4*256];
__device__ float g_wT0[27*32];
__device__ float g_wT1[288*64];
// conv3 weights frag layout: [(sb*9+tap)*2+cb][k4][ntg 32][lane 32] ull
__device__ ull g_w3f[27*2*4*32*32];
// conv2 weights frag layout: [(sb*9+tap)][k4][ntg 16][lane 32] ull
__device__ ull g_w2f[27*4*16*32];

// ---------------- packed f32x2 helpers ----------------
__device__ __forceinline__ void ffma2(ull &d, ull a, ull b) {
    asm("fma.rn.f32x2 %0, %1, %2, %0;" : "+l"(d) : "l"(a), "l"(b));
}
__device__ __forceinline__ ull bcast2(float v) {
    ull r; unsigned int u = __float_as_uint(v);
    asm("mov.b64 %0, {%1, %1};" : "=l"(r) : "r"(u));
    return r;
}
__device__ __forceinline__ void unpack2(float &lo, float &hi, ull v) {
    unsigned int l, h;
    asm("mov.b64 {%0, %1}, %2;" : "=r"(l), "=r"(h) : "l"(v));
    lo = __uint_as_float(l); hi = __uint_as_float(h);
}

// ---------------- mma helpers ----------------
__device__ __forceinline__ unsigned smem_u32(const void* p) {
    unsigned a;
    asm("{ .reg .u64 t; cvta.to.shared.u64 t, %1; cvt.u32.u64 %0, t; }" : "=r"(a) : "l"(p));
    return a;
}
__device__ __forceinline__ void ldsm4(unsigned &r0, unsigned &r1, unsigned &r2, unsigned &r3, unsigned addr) {
    asm volatile("ldmatrix.sync.aligned.m8n8.x4.shared.b16 {%0,%1,%2,%3}, [%4];"
        : "=r"(r0), "=r"(r1), "=r"(r2), "=r"(r3) : "r"(addr));
}
__device__ __forceinline__ void mma16816(float* d, const unsigned* a, unsigned b0, unsigned b1) {
    asm volatile("mma.sync.aligned.m16n8k16.row.col.f32.bf16.bf16.f32 "
        "{%0,%1,%2,%3}, {%4,%5,%6,%7}, {%8,%9}, {%0,%1,%2,%3};"
        : "+f"(d[0]), "+f"(d[1]), "+f"(d[2]), "+f"(d[3])
        : "r"(a[0]), "r"(a[1]), "r"(a[2]), "r"(a[3]), "r"(b0), "r"(b1));
}
__device__ __forceinline__ void cpasync16(unsigned dst, const void* src) {
    asm volatile("cp.async.cg.shared.global [%0], [%1], 16;" :: "r"(dst), "l"(src));
}
#define CP_COMMIT() asm volatile("cp.async.commit_group;" ::: "memory")
#define CP_WAIT1()  asm volatile("cp.async.wait_group 1;" ::: "memory")

__device__ __forceinline__ void split3(float v, __nv_bfloat16 &h, __nv_bfloat16 &m, __nv_bfloat16 &l) {
    h = __float2bfloat16(v);
    float r = v - __bfloat162float(h);
    m = __float2bfloat16(r);
    l = __float2bfloat16(r - __bfloat162float(m));
}

// ---------------- BN fold ----------------
struct FoldArgs { const float* cb[4]; const float* g[4]; const float* bt[4];
                  const float* rm[4]; const float* rv[4]; };
__global__ void fold_all_kernel(FoldArgs a)
{
    const int nchs[4] = {32, 64, 128, 256};
    int l = blockIdx.x, c = threadIdx.x;
    if (c < nchs[l]) {
        float s = a.g[l][c] / sqrtf(a.rv[l][c] + 1e-5f);
        g_scale[l*256 + c] = s;
        g_bias[l*256 + c]  = a.cb[l][c]*s + a.bt[l][c] - a.rm[l][c]*s;
    }
}

// ---------------- weight transpose (fp32 convs) ----------------
__global__ void wt_kernel(const float* __restrict__ w, float* __restrict__ dst,
                          int cin9, int cout)
{
    int idx = blockIdx.x * 256 + threadIdx.x;
    if (idx < cin9 * cout) {
        int s  = idx / cout;
        int co = idx - s * cout;
        dst[idx] = w[(long)co * cin9 + s];
    }
}

// ---------------- conv3 weight -> bf16 split fragment layout ----------------
__global__ void w3frag_kernel(const float* __restrict__ w3, unsigned* __restrict__ dst)
{
    int idx = blockIdx.x * 256 + threadIdx.x;
    if (idx >= 27*2*4*32*32*2) return;
    int t = idx;
    int r    = t & 1;  t >>= 1;
    int lane = t & 31; t >>= 5;
    int nt   = t & 31; t >>= 5;
    int k4   = t & 3;  t >>= 2;
    int cb   = t & 1;  t >>= 1;
    int tap  = t % 9;
    int sb   = t / 9;
    int n  = nt*8 + (lane >> 2);
    int k0 = (lane & 3)*2 + r*8;
    unsigned out = 0;
#pragma unroll
    for (int e = 0; e < 2; e++) {
        int cin = cb*64 + k4*16 + k0 + e;
        float v = w3[((long)n*128 + cin)*9 + tap];
        __nv_bfloat16 h, m, l; split3(v, h, m, l);
        __nv_bfloat16 sel = (sb == 0) ? h : (sb == 1 ? m : l);
        out |= ((unsigned)__bfloat16_as_ushort(sel)) << (16*e);
    }
    dst[idx] = out;
}

// ---------------- conv2 weight -> bf16 split fragment layout ----------------
__global__ void w2frag_kernel(const float* __restrict__ w2, unsigned* __restrict__ dst)
{
    int idx = blockIdx.x * 256 + threadIdx.x;
    if (idx >= 27*4*16*32*2) return;
    int t = idx;
    int r    = t & 1;  t >>= 1;
    int lane = t & 31; t >>= 5;
    int nt   = t & 15; t >>= 4;
    int k4   = t & 3;  t >>= 2;
    int tap  = t % 9;
    int sb   = t / 9;
    int n  = nt*8 + (lane >> 2);
    int k0 = (lane & 3)*2 + r*8;
    unsigned out = 0;
#pragma unroll
    for (int e = 0; e < 2; e++) {
        int cin = k4*16 + k0 + e;
        float v = w2[((long)n*64 + cin)*9 + tap];
        __nv_bfloat16 h, m, l; split3(v, h, m, l);
        __nv_bfloat16 sel = (sb == 0) ? h : (sb == 1 ? m : l);
        out |= ((unsigned)__bfloat16_as_ushort(sel)) << (16*e);
    }
    dst[idx] = out;
}

// ================= X staging (3 bf16 splits, 64 cin, 16x16 + halo) ==========
__device__ __forceinline__ void stageX(__nv_bfloat16* Xs, const float* inb, int tid)
{
    for (int i = tid; i < 324*32; i += 256) {
        int row = i >> 5, cp = i & 31;
        int y = row / 18, x = row - y*18;
        int gy = y - 1, gx = x - 1;
        float v0 = 0.f, v1 = 0.f;
        if ((unsigned)gy < 16u && (unsigned)gx < 16u) {
            v0 = inb[(2*cp  )*256 + gy*16 + gx];
            v1 = inb[(2*cp+1)*256 + gy*16 + gx];
        }
        __nv_bfloat16 h0, m0, l0, h1, m1, l1;
        split3(v0, h0, m0, l0); split3(v1, h1, m1, l1);
        unsigned* p0 = (unsigned*)((char*)Xs + row*144 + cp*4);
        p0[0]                             = ((unsigned)__bfloat16_as_ushort(h1) << 16) | __bfloat16_as_ushort(h0);
        *(unsigned*)((char*)p0 + 46656)   = ((unsigned)__bfloat16_as_ushort(m1) << 16) | __bfloat16_as_ushort(m0);
        *(unsigned*)((char*)p0 + 2*46656) = ((unsigned)__bfloat16_as_ushort(l1) << 16) | __bfloat16_as_ushort(l0);
    }
}

#define X_BYTES 139968
#define W_BYTES 24576
#define SM_MMA  (X_BYTES + 2*W_BYTES)   // 189120

// ---- shared mainloop body for one step: warp = M 64px (mg) x N 32 (ng) -----
__device__ __forceinline__ void mma_step(const char* smb, unsigned Xb, int stepbuf,
                                         int tap, int mg, int ng,
                                         unsigned xr, unsigned hs16,
                                         float acc[4][4][4])
{
    const ull* wS = (const ull*)(smb + X_BYTES + stepbuf * W_BYTES);
    const int dy = tap / 3, dx = tap - dy*3;
    const unsigned rowbase = (unsigned)((4*mg + dy)*18 + xr + dx);
    for (int sa = 0; sa < 3; sa++) {
        unsigned aF[4][4][4];
#pragma unroll
        for (int k4 = 0; k4 < 4; k4++)
#pragma unroll
            for (int mt = 0; mt < 4; mt++) {
                unsigned addr = Xb + (unsigned)sa*46656u
                              + (rowbase + mt*18)*144u + k4*32u + hs16;
                ldsm4(aF[k4][mt][0], aF[k4][mt][1], aF[k4][mt][2], aF[k4][mt][3], addr);
            }
        const int nsb = 3 - sa;
        for (int sb = 0; sb < nsb; sb++) {
            const ull* wSb = wS + sb*1024 + ng*4*32 + (unsigned)(threadIdx.x & 31);
#pragma unroll
            for (int k4 = 0; k4 < 4; k4++) {
#pragma unroll
                for (int nt = 0; nt < 4; nt++) {
                    ull bv = wSb[(k4*8 + nt)*32];
                    unsigned b0 = (unsigned)bv, b1 = (unsigned)(bv >> 32);
#pragma unroll
                    for (int mt = 0; mt < 4; mt++)
                        mma16816(acc[mt][nt], aF[k4][mt], b0, b1);
                }
            }
        }
    }
}

// ---------------- conv3: mma.sync, cp.async weights, new tiling -------------
__global__ __launch_bounds__(256, 1)
void conv3_mma_kernel()
{
    extern __shared__ __nv_bfloat16 Xs[];
    char* smb = (char*)Xs;
    const unsigned Xb = smem_u32(Xs);
    const int tid = threadIdx.x, wid = tid >> 5, lane = tid & 31;
    const int mg = wid >> 1, ng = wid & 1;
    const int b = blockIdx.x >> 2, nq = blockIdx.x & 3;
    const int n0 = nq * 64;

    float acc[4][4][4];
#pragma unroll
    for (int mt = 0; mt < 4; mt++)
#pragma unroll
        for (int nt = 0; nt < 4; nt++)
#pragma unroll
            for (int c = 0; c < 4; c++) acc[mt][nt][c] = 0.f;

    const unsigned xr = lane & 15;
    const unsigned hs16 = ((lane >> 4) & 1) * 16;

    {
        for (int j = tid; j < 1536; j += 256) {
            int sb = j >> 9, rem = j & 511;
            int k4 = rem >> 7, rem2 = rem & 127;
            const ull* src = g_w3f + ((long)(sb*9 + 0)*2 + 0)*4096 + k4*1024 + nq*256 + rem2*2;
            cpasync16(Xb + X_BYTES + (unsigned)j*16, src);
        }
        CP_COMMIT();
    }

    for (int step = 0; step < 18; step++) {
        const int cb = step / 9, tap = step % 9;
        if (tap == 0) {
            stageX(Xs, g_act2 + ((long)b*128 + cb*64) * 256, tid);
            __syncthreads();
        }
        if (step + 1 < 18) {
            const int ns = step + 1, ncb = ns / 9, ntap = ns % 9;
            const unsigned wdst = Xb + X_BYTES + (unsigned)((ns & 1) * W_BYTES);
            for (int j = tid; j < 1536; j += 256) {
                int sb = j >> 9, rem = j & 511;
                int k4 = rem >> 7, rem2 = rem & 127;
                const ull* src = g_w3f + ((long)(sb*9 + ntap)*2 + ncb)*4096 + k4*1024 + nq*256 + rem2*2;
                cpasync16(wdst + (unsigned)j*16, src);
            }
        }
        CP_COMMIT();
        CP_WAIT1();
        __syncthreads();
        mma_step(smb, Xb, step & 1, tap, mg, ng, xr, hs16, acc);
        __syncthreads();
    }

    // ---------- epilogue: BN + relu + maxpool2x2 + mean ----------
    float* sRed = (float*)Xs;     // [8 pooled rows][64 couts]
#pragma unroll
    for (int p = 0; p < 2; p++) { // pooled row = 2*mg + p, from mt pair (2p, 2p+1)
#pragma unroll
        for (int nt = 0; nt < 4; nt++) {
            const int co = n0 + ng*32 + nt*8 + (lane & 3)*2;
            const float s0c = g_scale[768 + co],     b0c = g_bias[768 + co];
            const float s1c = g_scale[768 + co + 1], b1c = g_bias[768 + co + 1];
            float q0 = fmaxf(fmaxf(fmaf(acc[2*p][nt][0], s0c, b0c), 0.f),
                             fmaxf(fmaf(acc[2*p+1][nt][0], s0c, b0c), 0.f));
            float q1 = fmaxf(fmaxf(fmaf(acc[2*p][nt][1], s1c, b1c), 0.f),
                             fmaxf(fmaf(acc[2*p+1][nt][1], s1c, b1c), 0.f));
            float q2 = fmaxf(fmaxf(fmaf(acc[2*p][nt][2], s0c, b0c), 0.f),
                             fmaxf(fmaf(acc[2*p+1][nt][2], s0c, b0c), 0.f));
            float q3 = fmaxf(fmaxf(fmaf(acc[2*p][nt][3], s1c, b1c), 0.f),
                             fmaxf(fmaf(acc[2*p+1][nt][3], s1c, b1c), 0.f));
            q0 = fmaxf(q0, __shfl_xor_sync(0xffffffffu, q0, 4));
            q1 = fmaxf(q1, __shfl_xor_sync(0xffffffffu, q1, 4));
            q2 = fmaxf(q2, __shfl_xor_sync(0xffffffffu, q2, 4));
            q3 = fmaxf(q3, __shfl_xor_sync(0xffffffffu, q3, 4));
            float s0 = q0 + q2, s1 = q1 + q3;
            s0 += __shfl_xor_sync(0xffffffffu, s0, 8);
            s0 += __shfl_xor_sync(0xffffffffu, s0, 16);
            s1 += __shfl_xor_sync(0xffffffffu, s1, 8);
            s1 += __shfl_xor_sync(0xffffffffu, s1, 16);
            if (lane < 4) {
                sRed[(2*mg + p)*64 + ng*32 + nt*8 + lane*2]     = s0;
                sRed[(2*mg + p)*64 + ng*32 + nt*8 + lane*2 + 1] = s1;
            }
        }
    }
    __syncthreads();
    if (tid < 64) {
        float f = 0.f;
#pragma unroll
        for (int pr = 0; pr < 8; pr++) f += sRed[pr*64 + tid];
        g_feats[b*256 + n0 + tid] = f * (1.0f/64.0f);
    }
}

// ---------------- conv2: mma.sync, cp.async weights, new tiling -------------
__global__ __launch_bounds__(256, 1)
void conv2_mma_kernel()
{
    extern __shared__ __nv_bfloat16 Xs[];
    char* smb = (char*)Xs;
    const unsigned Xb = smem_u32(Xs);
    const int tid = threadIdx.x, wid = tid >> 5, lane = tid & 31;
    const int mg = wid >> 1, ng = wid & 1;
    const int b = blockIdx.x >> 1, nq = blockIdx.x & 1;
    const int n0 = nq * 64;

    float acc[4][4][4];
#pragma unroll
    for (int mt = 0; mt < 4; mt++)
#pragma unroll
        for (int nt = 0; nt < 4; nt++)
#pragma unroll
            for (int c = 0; c < 4; c++) acc[mt][nt][c] = 0.f;

    const unsigned xr = lane & 15;
    const unsigned hs16 = ((lane >> 4) & 1) * 16;

    {
        for (int j = tid; j < 1536; j += 256) {
            int sb = j >> 9, rem = j & 511;
            int k4 = rem >> 7, rem2 = rem & 127;
            const ull* src = g_w2f + ((long)(sb*9 + 0)*4 + k4)*512 + nq*256 + rem2*2;
            cpasync16(Xb + X_BYTES + (unsigned)j*16, src);
        }
        CP_COMMIT();
    }
    stageX(Xs, g_act1 + (long)b*64*256, tid);
    __syncthreads();

    for (int step = 0; step < 9; step++) {
        if (step + 1 < 9) {
            const unsigned wdst = Xb + X_BYTES + (unsigned)(((step+1) & 1) * W_BYTES);
            const int ntap = step + 1;
            for (int j = tid; j < 1536; j += 256) {
                int sb = j >> 9, rem = j & 511;
                int k4 = rem >> 7, rem2 = rem & 127;
                const ull* src = g_w2f + ((long)(sb*9 + ntap)*4 + k4)*512 + nq*256 + rem2*2;
                cpasync16(wdst + (unsigned)j*16, src);
            }
        }
        CP_COMMIT();
        CP_WAIT1();
        __syncthreads();
        mma_step(smb, Xb, step & 1, step, mg, ng, xr, hs16, acc);
        __syncthreads();
    }

    // ---------- epilogue: BN + relu, smem stage, coalesced store ----------
    float* sOut = (float*)Xs;   // [64 co][stride 264]
#pragma unroll
    for (int nt = 0; nt < 4; nt++) {
        const int co_l = ng*32 + nt*8 + (lane & 3)*2;
        const int co = n0 + co_l;
        const float s0c = g_scale[512 + co],     b0c = g_bias[512 + co];
        const float s1c = g_scale[512 + co + 1], b1c = g_bias[512 + co + 1];
        const int x0 = lane >> 2;
#pragma unroll
        for (int mt = 0; mt < 4; mt++) {
            const int y = 4*mg + mt;
            float v0 = fmaxf(fmaf(acc[mt][nt][0], s0c, b0c), 0.f);
            float v1 = fmaxf(fmaf(acc[mt][nt][1], s1c, b1c), 0.f);
            float v2 = fmaxf(fmaf(acc[mt][nt][2], s0c, b0c), 0.f);
            float v3 = fmaxf(fmaf(acc[mt][nt][3], s1c, b1c), 0.f);
            sOut[(co_l  )*264 + y*16 + x0]     = v0;
            sOut[(co_l+1)*264 + y*16 + x0]     = v1;
            sOut[(co_l  )*264 + y*16 + x0 + 8] = v2;
            sOut[(co_l+1)*264 + y*16 + x0 + 8] = v3;
        }
    }
    __syncthreads();
    for (int i = tid; i < 64*256; i += 256) {
        int co = i >> 8, pix = i & 255;
        g_act2[((long)b*128 + n0 + co)*256 + pix] = sOut[co*264 + pix];
    }
}

// ---------------- conv3x3 fp32 (layers 0-1) ----------------
template<int LAYER, int CIN, int CCH, int COUT, int H, bool POOL>
__global__ __launch_bounds__(256, 2)
void conv_kernel(const float* __restrict__ x, const float* __restrict__ wT)
{
    const float* in = (LAYER == 0) ? x : g_act0;

    const int b   = blockIdx.z;
    const int ct  = blockIdx.x;
    const int ntx = H / 16;
    const int tyi = blockIdx.y / ntx, txi = blockIdx.y % ntx;
    const int ty0 = tyi * 16, tx0 = txi * 16;

    const int tid = threadIdx.x;
    const int cg  = tid >> 6;
    const int p   = tid & 63;
    const int py  = p >> 3, px = p & 7;
    const int oy  = 2*py,  ox = 2*px;

    extern __shared__ ull sIn2[];

    ull acc2[4][4];
#pragma unroll
    for (int i = 0; i < 4; i++)
#pragma unroll
        for (int k = 0; k < 4; k++) acc2[i][k] = 0ull;

    const int NCH = CIN / CCH;
    const int co0 = ct*32 + cg*8;

    for (int ch = 0; ch < NCH; ch++) {
        if (ch) __syncthreads();
        const float* inb = in + ((long)b*CIN + (long)ch*CCH) * H * H;
        for (int i = tid; i < CCH*324; i += 256) {
            int c = i / 324; int r = i - c*324;
            int y = r / 18,  xx = r - y*18;
            int gy = ty0 + y - 1, gx = tx0 + xx - 1;
            float v = 0.f;
            if ((unsigned)gy < (unsigned)H && (unsigned)gx < (unsigned)H)
                v = inb[(long)c*H*H + gy*H + gx];
            sIn2[c*360 + y*20 + xx] = bcast2(v);
        }
        __syncthreads();

        const float* wrow = wT + ((long)(ch*CCH)*9)*COUT + co0;
#pragma unroll 1
        for (int c = 0; c < CCH; c++) {
            const ull* sic = sIn2 + c*360 + oy*20 + ox;
            ull iv[4][4];
#pragma unroll
            for (int dy = 0; dy < 4; dy++) {
                ulonglong2 a0 = *(const ulonglong2*)(sic + dy*20);
                ulonglong2 a1 = *(const ulonglong2*)(sic + dy*20 + 2);
                iv[dy][0] = a0.x; iv[dy][1] = a0.y;
                iv[dy][2] = a1.x; iv[dy][3] = a1.y;
            }
            const float* wr = wrow + (long)c*9*COUT;
#pragma unroll
            for (int t = 0; t < 9; t++) {
                ulonglong2 w01 = __ldg((const ulonglong2*)(wr + t*COUT));
                ulonglong2 w23 = __ldg((const ulonglong2*)(wr + t*COUT + 4));
                const int dy = t / 3, dx = t % 3;
                ffma2(acc2[0][0], iv[dy  ][dx  ], w01.x);
                ffma2(acc2[0][1], iv[dy  ][dx  ], w01.y);
                ffma2(acc2[0][2], iv[dy  ][dx  ], w23.x);
                ffma2(acc2[0][3], iv[dy  ][dx  ], w23.y);
                ffma2(acc2[1][0], iv[dy  ][dx+1], w01.x);
                ffma2(acc2[1][1], iv[dy  ][dx+1], w01.y);
                ffma2(acc2[1][2], iv[dy  ][dx+1], w23.x);
                ffma2(acc2[1][3], iv[dy  ][dx+1], w23.y);
                ffma2(acc2[2][0], iv[dy+1][dx  ], w01.x);
                ffma2(acc2[2][1], iv[dy+1][dx  ], w01.y);
                ffma2(acc2[2][2], iv[dy+1][dx  ], w23.x);
                ffma2(acc2[2][3], iv[dy+1][dx  ], w23.y);
                ffma2(acc2[3][0], iv[dy+1][dx+1], w01.x);
                ffma2(acc2[3][1], iv[dy+1][dx+1], w01.y);
                ffma2(acc2[3][2], iv[dy+1][dx+1], w23.x);
                ffma2(acc2[3][3], iv[dy+1][dx+1], w23.y);
            }
        }
    }

    float acc[4][8];
#pragma unroll
    for (int i = 0; i < 4; i++)
#pragma unroll
        for (int kk = 0; kk < 4; kk++)
            unpack2(acc[i][2*kk], acc[i][2*kk+1], acc2[i][kk]);

    float* outp = (LAYER == 0) ? g_act0 : g_act1;

    if (!POOL) {
#pragma unroll
        for (int k = 0; k < 8; k++) {
            const float s  = g_scale[LAYER*256 + co0 + k];
            const float bi = g_bias [LAYER*256 + co0 + k];
#pragma unroll
            for (int r = 0; r < 2; r++)
#pragma unroll
                for (int s2 = 0; s2 < 2; s2++) {
                    float v = fmaxf(fmaf(acc[r*2+s2][k], s, bi), 0.f);
                    outp[(((long)b*COUT + co0 + k)*H + (ty0+oy+r))*H + (tx0+ox+s2)] = v;
                }
        }
    } else {
        const int Ho = H / 2;
        const int gy = ty0/2 + py, gx = tx0/2 + px;
#pragma unroll
        for (int k = 0; k < 8; k++) {
            const float s  = g_scale[LAYER*256 + co0 + k];
            const float bi = g_bias [LAYER*256 + co0 + k];
            float v0 = fmaf(acc[0][k], s, bi);
            float v1 = fmaf(acc[1][k], s, bi);
            float v2 = fmaf(acc[2][k], s, bi);
            float v3 = fmaf(acc[3][k], s, bi);
            float pv = fmaxf(0.f, fmaxf(fmaxf(v0, v1), fmaxf(v2, v3)));
            outp[(((long)b*COUT + co0 + k)*Ho + gy)*Ho + gx] = pv;
        }
    }
}

// ---------------- classifier + log_softmax + conf ----------------
__global__ void classifier_kernel(const float* __restrict__ cls_w,
                                  const float* __restrict__ cls_b)
{
    const int b = blockIdx.x;
    const int tid = threadIdx.x;   // 128
    __shared__ float sf[256];
    __shared__ float sl[80];
    for (int i = tid; i < 256; i += 128) sf[i] = g_feats[b*256 + i];
    __syncthreads();
    if (tid < 80) {
        const float* wr = cls_w + (long)tid * 256;
        float s = 0.f;
#pragma unroll 8
        for (int k = 0; k < 256; k++) s = fmaf(sf[k], wr[k], s);
        s += cls_b[tid];
        sl[tid] = s;
        g_logits[(long)b*80 + tid] = s;
    }
    __syncthreads();
    if (tid < 8) {
        float m = -1e30f;
        for (int c = 0; c < 10; c++) m = fmaxf(m, sl[tid*10 + c]);
        float se = 0.f;
        for (int c = 0; c < 10; c++) se += expf(sl[tid*10 + c] - m);
        float lse = m + logf(se);
        float cf = 0.f;
        for (int c = 0; c < 10; c++) {
            float lp = sl[tid*10 + c] - lse;
            cf += expf(lp) * lp;
        }
        g_conf[b*8 + tid] = cf;
    }
}

// ---------------- greedy capacity router ----------------
__global__ __launch_bounds__(1024)
void route_kernel()
{
    __shared__ unsigned long long keys[4096];
    __shared__ unsigned char D[4096];
    __shared__ unsigned char sc[512];
    __shared__ int ec[8];
    __shared__ int assigned;

    const int tid = threadIdx.x;
    for (int i = tid; i < 4096; i += 1024) D[i] = 0;
    if (tid < 512) sc[tid] = 0;
    if (tid < 8)   ec[tid] = 0;
    if (tid == 0)  assigned = 0;
    __syncthreads();

    for (int cyc_i = 0; cyc_i < 4; cyc_i++) {
        for (int i = tid; i < 4096; i += 1024) {
            float v = g_conf[i];
            if (cyc_i > 0) v = v * (1.0f - (float)ec[i & 7] / 160.0f);
            unsigned int fb = __float_as_uint(v);
            unsigned int ou = (fb & 0x80000000u) ? ~fb : (fb | 0x80000000u);
            keys[i] = ((unsigned long long)(~ou) << 32) | (unsigned int)i;
        }
        __syncthreads();
        for (int k2 = 2; k2 <= 4096; k2 <<= 1) {
            for (int j = k2 >> 1; j > 0; j >>= 1) {
                for (int i = tid; i < 4096; i += 1024) {
                    int ixj = i ^ j;
                    if (ixj > i) {
                        unsigned long long a = keys[i], bb = keys[ixj];
                        bool up = ((i & k2) == 0);
                        if ((a > bb) == up) { keys[i] = bb; keys[ixj] = a; }
                    }
                }
                __syncthreads();
            }
        }
        if (tid == 0) {
            int cyc = 0, asg = assigned;
            for (int s = 0; s < 4096; s++) {
                if (cyc >= 256 || asg >= 1024) break;
                int id = (int)(keys[s] & 0xFFFFFFFFull);
                int jj = id & 7, bb = id >> 3;
                if (!D[id] && ec[jj] < 160 && sc[bb] < 2) {
                    D[id] = 1; ec[jj]++; sc[bb]++; asg++; cyc++;
                }
            }
            assigned = asg;
        }
        __syncthreads();
    }
    for (int i = tid; i < 4096; i += 1024) g_D[i] = (int)D[i];
}

// ---------------- final combine ----------------
__global__ void final_kernel(float* __restrict__ out, int out_size)
{
    const int b = blockIdx.x;
    const int lane = threadIdx.x;
    int nd = 0;
#pragma unroll
    for (int e = 0; e < 8; e++) nd += g_D[b*8 + e];
    float norm = fmaxf((float)nd, 1.0f);
    if (lane < 10) {
        float s = 0.f;
#pragma unroll
        for (int e = 0; e < 8; e++) {
            if (g_D[b*8 + e])
                s += g_conf[b*8 + e] * g_logits[(long)(b*8 + e)*10 + lane];
        }
        out[b*10 + lane] = s / norm;
    }
    if (out_size >= 5120 + 4096 && lane < 8)
        out[5120 + b*8 + lane] = g_conf[b*8 + lane];
    if (out_size >= 5120 + 8192 && lane < 8)
        out[5120 + 4096 + b*8 + lane] = g_D[b*8 + lane] ? 1.0f : 0.0f;
}

// ---------------- launch ----------------
extern "C" void kernel_launch(void* const* d_in, const int* in_sizes, int n_in,
                              void* d_out, int out_size)
{
    const float* x = (const float*)d_in[0];
    FoldArgs fa;
    const float* w[4];
    for (int i = 0; i < 4; i++) {
        w [i]    = (const float*)d_in[1 + i*6 + 0];
        fa.cb[i] = (const float*)d_in[1 + i*6 + 1];
        fa.g [i] = (const float*)d_in[1 + i*6 + 2];
        fa.bt[i] = (const float*)d_in[1 + i*6 + 3];
        fa.rm[i] = (const float*)d_in[1 + i*6 + 4];
        fa.rv[i] = (const float*)d_in[1 + i*6 + 5];
    }
    const float* cls_w = (const float*)d_in[25];
    const float* cls_b = (const float*)d_in[26];

    const int SM3  = 3  * 360 * 8;
    const int SM32 = 32 * 360 * 8;
    cudaFuncSetAttribute(conv_kernel<1,32, 32, 64,32,true >, cudaFuncAttributeMaxDynamicSharedMemorySize, SM32);
    cudaFuncSetAttribute(conv2_mma_kernel, cudaFuncAttributeMaxDynamicSharedMemorySize, SM_MMA);
    cudaFuncSetAttribute(conv3_mma_kernel, cudaFuncAttributeMaxDynamicSharedMemorySize, SM_MMA);

    fold_all_kernel<<<4, 256>>>(fa);

    float* wT0; float* wT1; unsigned* w3f; unsigned* w2f;
    cudaGetSymbolAddress((void**)&wT0, g_wT0);
    cudaGetSymbolAddress((void**)&wT1, g_wT1);
    cudaGetSymbolAddress((void**)&w3f, g_w3f);
    cudaGetSymbolAddress((void**)&w2f, g_w2f);
    wt_kernel<<<(27*32  + 255)/256, 256>>>(w[0], wT0, 27,  32);
    wt_kernel<<<(288*64 + 255)/256, 256>>>(w[1], wT1, 288, 64);
    w3frag_kernel<<<(27*2*4*32*32*2 + 255)/256, 256>>>(w[3], w3f);
    w2frag_kernel<<<(27*4*16*32*2   + 255)/256, 256>>>(w[2], w2f);

    conv_kernel<0,3,  3, 32,32,false><<<dim3(1,4,512), 256, SM3 >>>(x, wT0);
    conv_kernel<1,32, 32, 64,32,true ><<<dim3(2,4,512), 256, SM32>>>(x, wT1);
    conv2_mma_kernel<<<1024, 256, SM_MMA>>>();
    conv3_mma_kernel<<<2048, 256, SM_MMA>>>();

    classifier_kernel<<<512, 128>>>(cls_w, cls_b);
    route_kernel<<<1, 1024>>>();
    final_kernel<<<512, 32>>>((float*)d_out, out_size);
}

// round 9
// speedup vs baseline: 1.0616x; 1.0616x over previous
#include <cuda_runtime.h>
#include <cuda_bf16.h>
#include <math.h>

typedef unsigned long long ull;

// ---------------- device scratch ----------------
__device__ float g_act0[512*32*32*32];
__device__ float g_act1[512*64*16*16];
__device__ float g_act2[512*128*16*16];
__device__ float g_feats[512*256];
__device__ float g_logits[512*8*10];
__device__ float g_conf[512*8];
__device__ int   g_D[512*8];
__device__ float g_scale[4*256];
__device__ float g_bias[4*256];
__device__ float g_wT0[27*32];
// conv3 weights frag: [(sb*9+tap)*2+cb][k4 4][ntg 32][lane 32] ull
__device__ ull g_w3f[27*2*4*32*32];
// conv2 weights frag: [(sb*9+tap)][k4 4][ntg 16][lane 32] ull
__device__ ull g_w2f[27*4*16*32];
// conv1 weights frag: [(sb*9+tap)][k4 2][ntg 8][lane 32] ull
__device__ ull g_w1f[27*2*8*32];

// ---------------- packed f32x2 helpers ----------------
__device__ __forceinline__ void ffma2(ull &d, ull a, ull b) {
    asm("fma.rn.f32x2 %0, %1, %2, %0;" : "+l"(d) : "l"(a), "l"(b));
}
__device__ __forceinline__ ull bcast2(float v) {
    ull r; unsigned int u = __float_as_uint(v);
    asm("mov.b64 %0, {%1, %1};" : "=l"(r) : "r"(u));
    return r;
}
__device__ __forceinline__ void unpack2(float &lo, float &hi, ull v) {
    unsigned int l, h;
    asm("mov.b64 {%0, %1}, %2;" : "=r"(l), "=r"(h) : "l"(v));
    lo = __uint_as_float(l); hi = __uint_as_float(h);
}

// ---------------- mma helpers ----------------
__device__ __forceinline__ unsigned smem_u32(const void* p) {
    unsigned a;
    asm("{ .reg .u64 t; cvta.to.shared.u64 t, %1; cvt.u32.u64 %0, t; }" : "=r"(a) : "l"(p));
    return a;
}
__device__ __forceinline__ void ldsm4(unsigned &r0, unsigned &r1, unsigned &r2, unsigned &r3, unsigned addr) {
    asm volatile("ldmatrix.sync.aligned.m8n8.x4.shared.b16 {%0,%1,%2,%3}, [%4];"
        : "=r"(r0), "=r"(r1), "=r"(r2), "=r"(r3) : "r"(addr));
}
__device__ __forceinline__ void mma16816(float* d, const unsigned* a, unsigned b0, unsigned b1) {
    asm volatile("mma.sync.aligned.m16n8k16.row.col.f32.bf16.bf16.f32 "
        "{%0,%1,%2,%3}, {%4,%5,%6,%7}, {%8,%9}, {%0,%1,%2,%3};"
        : "+f"(d[0]), "+f"(d[1]), "+f"(d[2]), "+f"(d[3])
        : "r"(a[0]), "r"(a[1]), "r"(a[2]), "r"(a[3]), "r"(b0), "r"(b1));
}
__device__ __forceinline__ void cpasync16(unsigned dst, const void* src) {
    asm volatile("cp.async.cg.shared.global [%0], [%1], 16;" :: "r"(dst), "l"(src));
}
#define CP_COMMIT() asm volatile("cp.async.commit_group;" ::: "memory")
#define CP_WAIT1()  asm volatile("cp.async.wait_group 1;" ::: "memory")

__device__ __forceinline__ void split3(float v, __nv_bfloat16 &h, __nv_bfloat16 &m, __nv_bfloat16 &l) {
    h = __float2bfloat16(v);
    float r = v - __bfloat162float(h);
    m = __float2bfloat16(r);
    l = __float2bfloat16(r - __bfloat162float(m));
}

// ---------------- BN fold ----------------
struct FoldArgs { const float* cb[4]; const float* g[4]; const float* bt[4];
                  const float* rm[4]; const float* rv[4]; };
__global__ void fold_all_kernel(FoldArgs a)
{
    const int nchs[4] = {32, 64, 128, 256};
    int l = blockIdx.x, c = threadIdx.x;
    if (c < nchs[l]) {
        float s = a.g[l][c] / sqrtf(a.rv[l][c] + 1e-5f);
        g_scale[l*256 + c] = s;
        g_bias[l*256 + c]  = a.cb[l][c]*s + a.bt[l][c] - a.rm[l][c]*s;
    }
}

// ---------------- weight transpose (conv0 fp32) ----------------
__global__ void wt_kernel(const float* __restrict__ w, float* __restrict__ dst,
                          int cin9, int cout)
{
    int idx = blockIdx.x * 256 + threadIdx.x;
    if (idx < cin9 * cout) {
        int s  = idx / cout;
        int co = idx - s * cout;
        dst[idx] = w[(long)co * cin9 + s];
    }
}

// ---------------- weight -> bf16 split fragment layouts ----------------
__global__ void w3frag_kernel(const float* __restrict__ w3, unsigned* __restrict__ dst)
{
    int idx = blockIdx.x * 256 + threadIdx.x;
    if (idx >= 27*2*4*32*32*2) return;
    int t = idx;
    int r    = t & 1;  t >>= 1;
    int lane = t & 31; t >>= 5;
    int nt   = t & 31; t >>= 5;
    int k4   = t & 3;  t >>= 2;
    int cb   = t & 1;  t >>= 1;
    int tap  = t % 9;
    int sb   = t / 9;
    int n  = nt*8 + (lane >> 2);
    int k0 = (lane & 3)*2 + r*8;
    unsigned out = 0;
#pragma unroll
    for (int e = 0; e < 2; e++) {
        int cin = cb*64 + k4*16 + k0 + e;
        float v = w3[((long)n*128 + cin)*9 + tap];
        __nv_bfloat16 h, m, l; split3(v, h, m, l);
        __nv_bfloat16 sel = (sb == 0) ? h : (sb == 1 ? m : l);
        out |= ((unsigned)__bfloat16_as_ushort(sel)) << (16*e);
    }
    dst[idx] = out;
}

__global__ void w2frag_kernel(const float* __restrict__ w2, unsigned* __restrict__ dst)
{
    int idx = blockIdx.x * 256 + threadIdx.x;
    if (idx >= 27*4*16*32*2) return;
    int t = idx;
    int r    = t & 1;  t >>= 1;
    int lane = t & 31; t >>= 5;
    int nt   = t & 15; t >>= 4;
    int k4   = t & 3;  t >>= 2;
    int tap  = t % 9;
    int sb   = t / 9;
    int n  = nt*8 + (lane >> 2);
    int k0 = (lane & 3)*2 + r*8;
    unsigned out = 0;
#pragma unroll
    for (int e = 0; e < 2; e++) {
        int cin = k4*16 + k0 + e;
        float v = w2[((long)n*64 + cin)*9 + tap];
        __nv_bfloat16 h, m, l; split3(v, h, m, l);
        __nv_bfloat16 sel = (sb == 0) ? h : (sb == 1 ? m : l);
        out |= ((unsigned)__bfloat16_as_ushort(sel)) << (16*e);
    }
    dst[idx] = out;
}

__global__ void w1frag_kernel(const float* __restrict__ w1, unsigned* __restrict__ dst)
{
    int idx = blockIdx.x * 256 + threadIdx.x;
    if (idx >= 27*2*8*32*2) return;
    int t = idx;
    int r    = t & 1;  t >>= 1;
    int lane = t & 31; t >>= 5;
    int nt   = t & 7;  t >>= 3;
    int k4   = t & 1;  t >>= 1;
    int tap  = t % 9;
    int sb   = t / 9;
    int n  = nt*8 + (lane >> 2);
    int k0 = (lane & 3)*2 + r*8;
    unsigned out = 0;
#pragma unroll
    for (int e = 0; e < 2; e++) {
        int cin = k4*16 + k0 + e;
        float v = w1[((long)n*32 + cin)*9 + tap];
        __nv_bfloat16 h, m, l; split3(v, h, m, l);
        __nv_bfloat16 sel = (sb == 0) ? h : (sb == 1 ? m : l);
        out |= ((unsigned)__bfloat16_as_ushort(sel)) << (16*e);
    }
    dst[idx] = out;
}

// ================= X staging: 64-cin variant (conv2/3) ======================
__device__ __forceinline__ void stageX(__nv_bfloat16* Xs, const float* inb, int tid)
{
    for (int i = tid; i < 324*32; i += 256) {
        int row = i >> 5, cp = i & 31;
        int y = row / 18, x = row - y*18;
        int gy = y - 1, gx = x - 1;
        float v0 = 0.f, v1 = 0.f;
        if ((unsigned)gy < 16u && (unsigned)gx < 16u) {
            v0 = inb[(2*cp  )*256 + gy*16 + gx];
            v1 = inb[(2*cp+1)*256 + gy*16 + gx];
        }
        __nv_bfloat16 h0, m0, l0, h1, m1, l1;
        split3(v0, h0, m0, l0); split3(v1, h1, m1, l1);
        unsigned* p0 = (unsigned*)((char*)Xs + row*144 + cp*4);
        p0[0]                             = ((unsigned)__bfloat16_as_ushort(h1) << 16) | __bfloat16_as_ushort(h0);
        *(unsigned*)((char*)p0 + 46656)   = ((unsigned)__bfloat16_as_ushort(m1) << 16) | __bfloat16_as_ushort(m0);
        *(unsigned*)((char*)p0 + 2*46656) = ((unsigned)__bfloat16_as_ushort(l1) << 16) | __bfloat16_as_ushort(l0);
    }
}

#define X_BYTES 139968
#define W_BYTES 24576
#define SM_MMA  (X_BYTES + 2*W_BYTES)   // 189120

// ---- R7 mainloop body: warp = M 32px (wid) x N 64, K4 = # k16 per tap ------
template<int K4N>
__device__ __forceinline__ void mma_stepT(const char* smb, unsigned Xb, int xbytes, int wbytes,
                                          int stepbuf, int tap, int wid, int lane,
                                          unsigned xr, unsigned hs16, int splitstride,
                                          float acc[2][8][4])
{
    const ull* wS = (const ull*)(smb + xbytes + stepbuf * wbytes);
    const int dy = tap / 3, dx = tap - dy*3;
    const unsigned rowbase = (unsigned)((2*wid + dy)*18 + xr + dx);
    const int rowpitch = (splitstride == 46656) ? 144 : 80;
    for (int sa = 0; sa < 3; sa++) {
        unsigned aF[K4N][2][4];
#pragma unroll
        for (int k4 = 0; k4 < K4N; k4++)
#pragma unroll
            for (int mt = 0; mt < 2; mt++) {
                unsigned addr = Xb + (unsigned)sa*(unsigned)splitstride
                              + (rowbase + mt*18)*(unsigned)rowpitch + k4*32u + hs16;
                ldsm4(aF[k4][mt][0], aF[k4][mt][1], aF[k4][mt][2], aF[k4][mt][3], addr);
            }
        const int nsb = 3 - sa;
        for (int sb = 0; sb < nsb; sb++) {
            const ull* wSb = wS + sb*(K4N*8*32) + lane;
#pragma unroll
            for (int k4 = 0; k4 < K4N; k4++) {
#pragma unroll
                for (int nt = 0; nt < 8; nt++) {
                    ull bv = wSb[(k4*8 + nt)*32];
                    unsigned b0 = (unsigned)bv, b1 = (unsigned)(bv >> 32);
                    mma16816(acc[0][nt], aF[k4][0], b0, b1);
                    mma16816(acc[1][nt], aF[k4][1], b0, b1);
                }
            }
        }
    }
}

// ---------------- conv3: mma.sync + cp.async (R7 tiling) --------------------
__global__ __launch_bounds__(256, 1)
void conv3_mma_kernel()
{
    extern __shared__ __nv_bfloat16 Xs[];
    char* smb = (char*)Xs;
    const unsigned Xb = smem_u32(Xs);
    const int tid = threadIdx.x, wid = tid >> 5, lane = tid & 31;
    const int b = blockIdx.x >> 2, nq = blockIdx.x & 3;
    const int n0 = nq * 64;

    float acc[2][8][4];
#pragma unroll
    for (int mt = 0; mt < 2; mt++)
#pragma unroll
        for (int nt = 0; nt < 8; nt++)
#pragma unroll
            for (int c = 0; c < 4; c++) acc[mt][nt][c] = 0.f;

    const unsigned xr = lane & 15;
    const unsigned hs16 = ((lane >> 4) & 1) * 16;

    {
        for (int j = tid; j < 1536; j += 256) {
            int sb = j >> 9, rem = j & 511;
            int k4 = rem >> 7, rem2 = rem & 127;
            const ull* src = g_w3f + ((long)(sb*9 + 0)*2 + 0)*4096 + k4*1024 + nq*256 + rem2*2;
            cpasync16(Xb + X_BYTES + (unsigned)j*16, src);
        }
        CP_COMMIT();
    }

    for (int step = 0; step < 18; step++) {
        const int cb = step / 9, tap = step % 9;
        if (tap == 0) {
            stageX(Xs, g_act2 + ((long)b*128 + cb*64) * 256, tid);
            __syncthreads();
        }
        if (step + 1 < 18) {
            const int ns = step + 1, ncb = ns / 9, ntap = ns % 9;
            const unsigned wdst = Xb + X_BYTES + (unsigned)((ns & 1) * W_BYTES);
            for (int j = tid; j < 1536; j += 256) {
                int sb = j >> 9, rem = j & 511;
                int k4 = rem >> 7, rem2 = rem & 127;
                const ull* src = g_w3f + ((long)(sb*9 + ntap)*2 + ncb)*4096 + k4*1024 + nq*256 + rem2*2;
                cpasync16(wdst + (unsigned)j*16, src);
            }
        }
        CP_COMMIT();
        CP_WAIT1();
        __syncthreads();
        mma_stepT<4>(smb, Xb, X_BYTES, W_BYTES, step & 1, tap, wid, lane, xr, hs16, 46656, acc);
        __syncthreads();
    }

    // ---------- epilogue: BN + relu + maxpool2x2 + mean ----------
    float* sRed = (float*)Xs;
#pragma unroll
    for (int nt = 0; nt < 8; nt++) {
        const int co = n0 + nt*8 + (lane & 3)*2;
        const float s0c = g_scale[768 + co],     b0c = g_bias[768 + co];
        const float s1c = g_scale[768 + co + 1], b1c = g_bias[768 + co + 1];
        float q0 = fmaxf(fmaxf(fmaf(acc[0][nt][0], s0c, b0c), 0.f),
                         fmaxf(fmaf(acc[1][nt][0], s0c, b0c), 0.f));
        float q1 = fmaxf(fmaxf(fmaf(acc[0][nt][1], s1c, b1c), 0.f),
                         fmaxf(fmaf(acc[1][nt][1], s1c, b1c), 0.f));
        float q2 = fmaxf(fmaxf(fmaf(acc[0][nt][2], s0c, b0c), 0.f),
                         fmaxf(fmaf(acc[1][nt][2], s0c, b0c), 0.f));
        float q3 = fmaxf(fmaxf(fmaf(acc[0][nt][3], s1c, b1c), 0.f),
                         fmaxf(fmaf(acc[1][nt][3], s1c, b1c), 0.f));
        q0 = fmaxf(q0, __shfl_xor_sync(0xffffffffu, q0, 4));
        q1 = fmaxf(q1, __shfl_xor_sync(0xffffffffu, q1, 4));
        q2 = fmaxf(q2, __shfl_xor_sync(0xffffffffu, q2, 4));
        q3 = fmaxf(q3, __shfl_xor_sync(0xffffffffu, q3, 4));
        float s0 = q0 + q2, s1 = q1 + q3;
        s0 += __shfl_xor_sync(0xffffffffu, s0, 8);
        s0 += __shfl_xor_sync(0xffffffffu, s0, 16);
        s1 += __shfl_xor_sync(0xffffffffu, s1, 8);
        s1 += __shfl_xor_sync(0xffffffffu, s1, 16);
        if (lane < 4) {
            sRed[wid*64 + nt*8 + lane*2]     = s0;
            sRed[wid*64 + nt*8 + lane*2 + 1] = s1;
        }
    }
    __syncthreads();
    if (tid < 64) {
        float f = 0.f;
#pragma unroll
        for (int w = 0; w < 8; w++) f += sRed[w*64 + tid];
        g_feats[b*256 + n0 + tid] = f * (1.0f/64.0f);
    }
}

// ---------------- conv2: mma.sync + cp.async (R7 tiling) --------------------
__global__ __launch_bounds__(256, 1)
void conv2_mma_kernel()
{
    extern __shared__ __nv_bfloat16 Xs[];
    char* smb = (char*)Xs;
    const unsigned Xb = smem_u32(Xs);
    const int tid = threadIdx.x, wid = tid >> 5, lane = tid & 31;
    const int b = blockIdx.x >> 1, nq = blockIdx.x & 1;
    const int n0 = nq * 64;

    float acc[2][8][4];
#pragma unroll
    for (int mt = 0; mt < 2; mt++)
#pragma unroll
        for (int nt = 0; nt < 8; nt++)
#pragma unroll
            for (int c = 0; c < 4; c++) acc[mt][nt][c] = 0.f;

    const unsigned xr = lane & 15;
    const unsigned hs16 = ((lane >> 4) & 1) * 16;

    {
        for (int j = tid; j < 1536; j += 256) {
            int sb = j >> 9, rem = j & 511;
            int k4 = rem >> 7, rem2 = rem & 127;
            const ull* src = g_w2f + ((long)(sb*9 + 0)*4 + k4)*512 + nq*256 + rem2*2;
            cpasync16(Xb + X_BYTES + (unsigned)j*16, src);
        }
        CP_COMMIT();
    }
    stageX(Xs, g_act1 + (long)b*64*256, tid);
    __syncthreads();

    for (int step = 0; step < 9; step++) {
        if (step + 1 < 9) {
            const unsigned wdst = Xb + X_BYTES + (unsigned)(((step+1) & 1) * W_BYTES);
            const int ntap = step + 1;
            for (int j = tid; j < 1536; j += 256) {
                int sb = j >> 9, rem = j & 511;
                int k4 = rem >> 7, rem2 = rem & 127;
                const ull* src = g_w2f + ((long)(sb*9 + ntap)*4 + k4)*512 + nq*256 + rem2*2;
                cpasync16(wdst + (unsigned)j*16, src);
            }
        }
        CP_COMMIT();
        CP_WAIT1();
        __syncthreads();
        mma_stepT<4>(smb, Xb, X_BYTES, W_BYTES, step & 1, step, wid, lane, xr, hs16, 46656, acc);
        __syncthreads();
    }

    float* sOut = (float*)Xs;   // [64 co][stride 264]
#pragma unroll
    for (int nt = 0; nt < 8; nt++) {
        const int co_l = nt*8 + (lane & 3)*2;
        const int co = n0 + co_l;
        const float s0c = g_scale[512 + co],     b0c = g_bias[512 + co];
        const float s1c = g_scale[512 + co + 1], b1c = g_bias[512 + co + 1];
        const int x0 = lane >> 2;
#pragma unroll
        for (int mt = 0; mt < 2; mt++) {
            const int y = 2*wid + mt;
            float v0 = fmaxf(fmaf(acc[mt][nt][0], s0c, b0c), 0.f);
            float v1 = fmaxf(fmaf(acc[mt][nt][1], s1c, b1c), 0.f);
            float v2 = fmaxf(fmaf(acc[mt][nt][2], s0c, b0c), 0.f);
            float v3 = fmaxf(fmaf(acc[mt][nt][3], s1c, b1c), 0.f);
            sOut[(co_l  )*264 + y*16 + x0]     = v0;
            sOut[(co_l+1)*264 + y*16 + x0]     = v1;
            sOut[(co_l  )*264 + y*16 + x0 + 8] = v2;
            sOut[(co_l+1)*264 + y*16 + x0 + 8] = v3;
        }
    }
    __syncthreads();
    for (int i = tid; i < 64*256; i += 256) {
        int co = i >> 8, pix = i & 255;
        g_act2[((long)b*128 + n0 + co)*256 + pix] = sOut[co*264 + pix];
    }
}

// ---------------- conv1: mma.sync + cp.async, 2 CTAs/SM ---------------------
// X1: 3 splits x 324 rows x 80B = 77760 B. W1: 1536 ull = 12288 B (x2 dbuf).
#define X1_BYTES 77760
#define W1_BYTES 12288
#define SM_MMA1  (X1_BYTES + 2*W1_BYTES)   // 102336
__global__ __launch_bounds__(256, 2)
void conv1_mma_kernel()
{
    extern __shared__ __nv_bfloat16 Xs[];
    char* smb = (char*)Xs;
    const unsigned Xb = smem_u32(Xs);
    const int tid = threadIdx.x, wid = tid >> 5, lane = tid & 31;
    const int b = blockIdx.x >> 2;
    const int tileq = blockIdx.x & 3;
    const int ty0 = (tileq >> 1) * 16, tx0 = (tileq & 1) * 16;

    float acc[2][8][4];
#pragma unroll
    for (int mt = 0; mt < 2; mt++)
#pragma unroll
        for (int nt = 0; nt < 8; nt++)
#pragma unroll
            for (int c = 0; c < 4; c++) acc[mt][nt][c] = 0.f;

    const unsigned xr = lane & 15;
    const unsigned hs16 = ((lane >> 4) & 1) * 16;

    // prefetch tap 0 weights: 768 chunks of 16B
    {
        for (int j = tid; j < 768; j += 256) {
            int sb = j >> 8, rem = j & 255;           // rem = k4*128 + rem2
            const ull* src = g_w1f + ((long)(sb*9 + 0)*2)*256 + rem*2;
            cpasync16(Xb + X1_BYTES + (unsigned)j*16, src);
        }
        CP_COMMIT();
    }
    // stage X: 32 cin, 18x18 halo, rows stride 80B
    {
        const float* inb = g_act0 + (long)b*32*1024;
        for (int i = tid; i < 324*16; i += 256) {
            int row = i >> 4, cp = i & 15;
            int y = row / 18, x = row - y*18;
            int gy = ty0 + y - 1, gx = tx0 + x - 1;
            float v0 = 0.f, v1 = 0.f;
            if ((unsigned)gy < 32u && (unsigned)gx < 32u) {
                v0 = inb[(2*cp  )*1024 + gy*32 + gx];
                v1 = inb[(2*cp+1)*1024 + gy*32 + gx];
            }
            __nv_bfloat16 h0, m0, l0, h1, m1, l1;
            split3(v0, h0, m0, l0); split3(v1, h1, m1, l1);
            unsigned* p0 = (unsigned*)(smb + row*80 + cp*4);
            p0[0]                          = ((unsigned)__bfloat16_as_ushort(h1) << 16) | __bfloat16_as_ushort(h0);
            *(unsigned*)((char*)p0 + 25920)   = ((unsigned)__bfloat16_as_ushort(m1) << 16) | __bfloat16_as_ushort(m0);
            *(unsigned*)((char*)p0 + 2*25920) = ((unsigned)__bfloat16_as_ushort(l1) << 16) | __bfloat16_as_ushort(l0);
        }
    }
    __syncthreads();

    for (int step = 0; step < 9; step++) {
        if (step + 1 < 9) {
            const unsigned wdst = Xb + X1_BYTES + (unsigned)(((step+1) & 1) * W1_BYTES);
            const int ntap = step + 1;
            for (int j = tid; j < 768; j += 256) {
                int sb = j >> 8, rem = j & 255;
                const ull* src = g_w1f + ((long)(sb*9 + ntap)*2)*256 + rem*2;
                cpasync16(wdst + (unsigned)j*16, src);
            }
        }
        CP_COMMIT();
        CP_WAIT1();
        __syncthreads();
        mma_stepT<2>(smb, Xb, X1_BYTES, W1_BYTES, step & 1, step, wid, lane, xr, hs16, 25920, acc);
        __syncthreads();
    }

    // ---------- epilogue: BN + relu + maxpool2x2, store to g_act1 ----------
    float* sOut = (float*)Xs;   // [64 co][stride 68], 8x8 pooled tile
#pragma unroll
    for (int nt = 0; nt < 8; nt++) {
        const int co_l = nt*8 + (lane & 3)*2;
        const int co = co_l;
        const float s0c = g_scale[256 + co],     b0c = g_bias[256 + co];
        const float s1c = g_scale[256 + co + 1], b1c = g_bias[256 + co + 1];
        // pool over y (mt 0,1) and x pairs (shfl 4)
        float q0 = fmaxf(fmaxf(fmaf(acc[0][nt][0], s0c, b0c), 0.f),
                         fmaxf(fmaf(acc[1][nt][0], s0c, b0c), 0.f));
        float q1 = fmaxf(fmaxf(fmaf(acc[0][nt][1], s1c, b1c), 0.f),
                         fmaxf(fmaf(acc[1][nt][1], s1c, b1c), 0.f));
        float q2 = fmaxf(fmaxf(fmaf(acc[0][nt][2], s0c, b0c), 0.f),
                         fmaxf(fmaf(acc[1][nt][2], s0c, b0c), 0.f));
        float q3 = fmaxf(fmaxf(fmaf(acc[0][nt][3], s1c, b1c), 0.f),
                         fmaxf(fmaf(acc[1][nt][3], s1c, b1c), 0.f));
        q0 = fmaxf(q0, __shfl_xor_sync(0xffffffffu, q0, 4));
        q1 = fmaxf(q1, __shfl_xor_sync(0xffffffffu, q1, 4));
        q2 = fmaxf(q2, __shfl_xor_sync(0xffffffffu, q2, 4));
        q3 = fmaxf(q3, __shfl_xor_sync(0xffffffffu, q3, 4));
        if (((lane >> 2) & 1) == 0) {
            const int px0 = (lane >> 2) >> 1;          // 0..3
            sOut[(co_l  )*68 + wid*8 + px0]     = q0;
            sOut[(co_l+1)*68 + wid*8 + px0]     = q1;
            sOut[(co_l  )*68 + wid*8 + px0 + 4] = q2;
            sOut[(co_l+1)*68 + wid*8 + px0 + 4] = q3;
        }
    }
    __syncthreads();
    {
        const int oy0 = ty0 >> 1, ox0 = tx0 >> 1;
        for (int i = tid; i < 64*64; i += 256) {
            int co = i >> 6, p = i & 63;
            int Y = p >> 3, X = p & 7;
            g_act1[((long)b*64 + co)*256 + (oy0 + Y)*16 + (ox0 + X)] = sOut[co*68 + p];
        }
    }
}

// ---------------- conv0 fp32 ----------------
__global__ __launch_bounds__(256, 2)
void conv0_kernel(const float* __restrict__ x, const float* __restrict__ wT)
{
    const int CIN = 3, COUT = 32, H = 32;
    const int b   = blockIdx.z;
    const int tyi = blockIdx.y / 2, txi = blockIdx.y % 2;
    const int ty0 = tyi * 16, tx0 = txi * 16;

    const int tid = threadIdx.x;
    const int cg  = tid >> 6;
    const int p   = tid & 63;
    const int py  = p >> 3, px = p & 7;
    const int oy  = 2*py,  ox = 2*px;

    extern __shared__ ull sIn2[];

    ull acc2[4][4];
#pragma unroll
    for (int i = 0; i < 4; i++)
#pragma unroll
        for (int k = 0; k < 4; k++) acc2[i][k] = 0ull;

    const int co0 = cg*8;

    const float* inb = x + (long)b*CIN*H*H;
    for (int i = tid; i < CIN*324; i += 256) {
        int c = i / 324; int r = i - c*324;
        int y = r / 18,  xx = r - y*18;
        int gy = ty0 + y - 1, gx = tx0 + xx - 1;
        float v = 0.f;
        if ((unsigned)gy < (unsigned)H && (unsigned)gx < (unsigned)H)
            v = inb[(long)c*H*H + gy*H + gx];
        sIn2[c*360 + y*20 + xx] = bcast2(v);
    }
    __syncthreads();

#pragma unroll
    for (int c = 0; c < CIN; c++) {
        const ull* sic = sIn2 + c*360 + oy*20 + ox;
        ull iv[4][4];
#pragma unroll
        for (int dy = 0; dy < 4; dy++) {
            ulonglong2 a0 = *(const ulonglong2*)(sic + dy*20);
            ulonglong2 a1 = *(const ulonglong2*)(sic + dy*20 + 2);
            iv[dy][0] = a0.x; iv[dy][1] = a0.y;
            iv[dy][2] = a1.x; iv[dy][3] = a1.y;
        }
        const float* wr = wT + (long)c*9*COUT + co0;
#pragma unroll
        for (int t = 0; t < 9; t++) {
            ulonglong2 w01 = __ldg((const ulonglong2*)(wr + t*COUT));
            ulonglong2 w23 = __ldg((const ulonglong2*)(wr + t*COUT + 4));
            const int dy = t / 3, dx = t % 3;
            ffma2(acc2[0][0], iv[dy  ][dx  ], w01.x);
            ffma2(acc2[0][1], iv[dy  ][dx  ], w01.y);
            ffma2(acc2[0][2], iv[dy  ][dx  ], w23.x);
            ffma2(acc2[0][3], iv[dy  ][dx  ], w23.y);
            ffma2(acc2[1][0], iv[dy  ][dx+1], w01.x);
            ffma2(acc2[1][1], iv[dy  ][dx+1], w01.y);
            ffma2(acc2[1][2], iv[dy  ][dx+1], w23.x);
            ffma2(acc2[1][3], iv[dy  ][dx+1], w23.y);
            ffma2(acc2[2][0], iv[dy+1][dx  ], w01.x);
            ffma2(acc2[2][1], iv[dy+1][dx  ], w01.y);
            ffma2(acc2[2][2], iv[dy+1][dx  ], w23.x);
            ffma2(acc2[2][3], iv[dy+1][dx  ], w23.y);
            ffma2(acc2[3][0], iv[dy+1][dx+1], w01.x);
            ffma2(acc2[3][1], iv[dy+1][dx+1], w01.y);
            ffma2(acc2[3][2], iv[dy+1][dx+1], w23.x);
            ffma2(acc2[3][3], iv[dy+1][dx+1], w23.y);
        }
    }

    float acc[4][8];
#pragma unroll
    for (int i = 0; i < 4; i++)
#pragma unroll
        for (int kk = 0; kk < 4; kk++)
            unpack2(acc[i][2*kk], acc[i][2*kk+1], acc2[i][kk]);

#pragma unroll
    for (int k = 0; k < 8; k++) {
        const float s  = g_scale[co0 + k];
        const float bi = g_bias [co0 + k];
#pragma unroll
        for (int r = 0; r < 2; r++)
#pragma unroll
            for (int s2 = 0; s2 < 2; s2++) {
                float v = fmaxf(fmaf(acc[r*2+s2][k], s, bi), 0.f);
                g_act0[(((long)b*32 + co0 + k)*H + (ty0+oy+r))*H + (tx0+ox+s2)] = v;
            }
    }
}

// ---------------- classifier + log_softmax + conf ----------------
__global__ void classifier_kernel(const float* __restrict__ cls_w,
                                  const float* __restrict__ cls_b)
{
    const int b = blockIdx.x;
    const int tid = threadIdx.x;   // 128
    __shared__ float sf[256];
    __shared__ float sl[80];
    for (int i = tid; i < 256; i += 128) sf[i] = g_feats[b*256 + i];
    __syncthreads();
    if (tid < 80) {
        const float* wr = cls_w + (long)tid * 256;
        float s = 0.f;
#pragma unroll 8
        for (int k = 0; k < 256; k++) s = fmaf(sf[k], wr[k], s);
        s += cls_b[tid];
        sl[tid] = s;
        g_logits[(long)b*80 + tid] = s;
    }
    __syncthreads();
    if (tid < 8) {
        float m = -1e30f;
        for (int c = 0; c < 10; c++) m = fmaxf(m, sl[tid*10 + c]);
        float se = 0.f;
        for (int c = 0; c < 10; c++) se += expf(sl[tid*10 + c] - m);
        float lse = m + logf(se);
        float cf = 0.f;
        for (int c = 0; c < 10; c++) {
            float lp = sl[tid*10 + c] - lse;
            cf += expf(lp) * lp;
        }
        g_conf[b*8 + tid] = cf;
    }
}

// ---------------- greedy capacity router ----------------
__global__ __launch_bounds__(1024)
void route_kernel()
{
    __shared__ unsigned long long keys[4096];
    __shared__ unsigned char D[4096];
    __shared__ unsigned char sc[512];
    __shared__ int ec[8];
    __shared__ int assigned;

    const int tid = threadIdx.x;
    for (int i = tid; i < 4096; i += 1024) D[i] = 0;
    if (tid < 512) sc[tid] = 0;
    if (tid < 8)   ec[tid] = 0;
    if (tid == 0)  assigned = 0;
    __syncthreads();

    for (int cyc_i = 0; cyc_i < 4; cyc_i++) {
        for (int i = tid; i < 4096; i += 1024) {
            float v = g_conf[i];
            if (cyc_i > 0) v = v * (1.0f - (float)ec[i & 7] / 160.0f);
            unsigned int fb = __float_as_uint(v);
            unsigned int ou = (fb & 0x80000000u) ? ~fb : (fb | 0x80000000u);
            keys[i] = ((unsigned long long)(~ou) << 32) | (unsigned int)i;
        }
        __syncthreads();
        for (int k2 = 2; k2 <= 4096; k2 <<= 1) {
            for (int j = k2 >> 1; j > 0; j >>= 1) {
                for (int i = tid; i < 4096; i += 1024) {
                    int ixj = i ^ j;
                    if (ixj > i) {
                        unsigned long long a = keys[i], bb = keys[ixj];
                        bool up = ((i & k2) == 0);
                        if ((a > bb) == up) { keys[i] = bb; keys[ixj] = a; }
                    }
                }
                __syncthreads();
            }
        }
        if (tid == 0) {
            int cyc = 0, asg = assigned;
            for (int s = 0; s < 4096; s++) {
                if (cyc >= 256 || asg >= 1024) break;
                int id = (int)(keys[s] & 0xFFFFFFFFull);
                int jj = id & 7, bb = id >> 3;
                if (!D[id] && ec[jj] < 160 && sc[bb] < 2) {
                    D[id] = 1; ec[jj]++; sc[bb]++; asg++; cyc++;
                }
            }
            assigned = asg;
        }
        __syncthreads();
    }
    for (int i = tid; i < 4096; i += 1024) g_D[i] = (int)D[i];
}

// ---------------- final combine ----------------
__global__ void final_kernel(float* __restrict__ out, int out_size)
{
    const int b = blockIdx.x;
    const int lane = threadIdx.x;
    int nd = 0;
#pragma unroll
    for (int e = 0; e < 8; e++) nd += g_D[b*8 + e];
    float norm = fmaxf((float)nd, 1.0f);
    if (lane < 10) {
        float s = 0.f;
#pragma unroll
        for (int e = 0; e < 8; e++) {
            if (g_D[b*8 + e])
                s += g_conf[b*8 + e] * g_logits[(long)(b*8 + e)*10 + lane];
        }
        out[b*10 + lane] = s / norm;
    }
    if (out_size >= 5120 + 4096 && lane < 8)
        out[5120 + b*8 + lane] = g_conf[b*8 + lane];
    if (out_size >= 5120 + 8192 && lane < 8)
        out[5120 + 4096 + b*8 + lane] = g_D[b*8 + lane] ? 1.0f : 0.0f;
}

// ---------------- launch ----------------
extern "C" void kernel_launch(void* const* d_in, const int* in_sizes, int n_in,
                              void* d_out, int out_size)
{
    const float* x = (const float*)d_in[0];
    FoldArgs fa;
    const float* w[4];
    for (int i = 0; i < 4; i++) {
        w [i]    = (const float*)d_in[1 + i*6 + 0];
        fa.cb[i] = (const float*)d_in[1 + i*6 + 1];
        fa.g [i] = (const float*)d_in[1 + i*6 + 2];
        fa.bt[i] = (const float*)d_in[1 + i*6 + 3];
        fa.rm[i] = (const float*)d_in[1 + i*6 + 4];
        fa.rv[i] = (const float*)d_in[1 + i*6 + 5];
    }
    const float* cls_w = (const float*)d_in[25];
    const float* cls_b = (const float*)d_in[26];

    const int SM3 = 3 * 360 * 8;
    cudaFuncSetAttribute(conv1_mma_kernel, cudaFuncAttributeMaxDynamicSharedMemorySize, SM_MMA1);
    cudaFuncSetAttribute(conv2_mma_kernel, cudaFuncAttributeMaxDynamicSharedMemorySize, SM_MMA);
    cudaFuncSetAttribute(conv3_mma_kernel, cudaFuncAttributeMaxDynamicSharedMemorySize, SM_MMA);

    fold_all_kernel<<<4, 256>>>(fa);

    float* wT0; unsigned* w3f; unsigned* w2f; unsigned* w1f;
    cudaGetSymbolAddress((void**)&wT0, g_wT0);
    cudaGetSymbolAddress((void**)&w3f, g_w3f);
    cudaGetSymbolAddress((void**)&w2f, g_w2f);
    cudaGetSymbolAddress((void**)&w1f, g_w1f);
    wt_kernel<<<(27*32 + 255)/256, 256>>>(w[0], wT0, 27, 32);
    w1frag_kernel<<<(27*2*8*32*2    + 255)/256, 256>>>(w[1], w1f);
    w2frag_kernel<<<(27*4*16*32*2   + 255)/256, 256>>>(w[2], w2f);
    w3frag_kernel<<<(27*2*4*32*32*2 + 255)/256, 256>>>(w[3], w3f);

    conv0_kernel<<<dim3(1,4,512), 256, SM3>>>(x, wT0);
    conv1_mma_kernel<<<2048, 256, SM_MMA1>>>();
    conv2_mma_kernel<<<1024, 256, SM_MMA>>>();
    conv3_mma_kernel<<<2048, 256, SM_MMA>>>();

    classifier_kernel<<<512, 128>>>(cls_w, cls_b);
    route_kernel<<<1, 1024>>>();
    final_kernel<<<512, 32>>>((float*)d_out, out_size);
}

// round 11
// speedup vs baseline: 1.0731x; 1.0108x over previous
#include <cuda_runtime.h>
#include <cuda_bf16.h>
#include <math.h>

typedef unsigned long long ull;

// ---------------- device scratch ----------------
__device__ float g_act0[512*32*32*32];
__device__ float g_act1[512*64*16*16];
__device__ float g_act2[512*128*16*16];
__device__ float g_feats[512*256];
__device__ float g_logits[512*8*10];
__device__ float g_conf[512*8];
__device__ int   g_D[512*8];
__device__ float g_scale[4*256];
__device__ float g_bias[4*256];
__device__ float g_wT0[27*32];
// conv3 weights frag: [(sb*9+tap)*2+cb64][k4 4][ntg 32][lane 32] ull
__device__ ull g_w3f[27*2*4*32*32];
// conv2 weights frag: [(sb*9+tap)][k4 4][ntg 16][lane 32] ull
__device__ ull g_w2f[27*4*16*32];
// conv1 weights frag: [(sb*9+tap)][k4 2][ntg 8][lane 32] ull
__device__ ull g_w1f[27*2*8*32];

// ---------------- packed f32x2 helpers ----------------
__device__ __forceinline__ void ffma2(ull &d, ull a, ull b) {
    asm("fma.rn.f32x2 %0, %1, %2, %0;" : "+l"(d) : "l"(a), "l"(b));
}
__device__ __forceinline__ ull bcast2(float v) {
    ull r; unsigned int u = __float_as_uint(v);
    asm("mov.b64 %0, {%1, %1};" : "=l"(r) : "r"(u));
    return r;
}
__device__ __forceinline__ void unpack2(float &lo, float &hi, ull v) {
    unsigned int l, h;
    asm("mov.b64 {%0, %1}, %2;" : "=r"(l), "=r"(h) : "l"(v));
    lo = __uint_as_float(l); hi = __uint_as_float(h);
}

// ---------------- mma helpers ----------------
__device__ __forceinline__ unsigned smem_u32(const void* p) {
    unsigned a;
    asm("{ .reg .u64 t; cvta.to.shared.u64 t, %1; cvt.u32.u64 %0, t; }" : "=r"(a) : "l"(p));
    return a;
}
__device__ __forceinline__ void ldsm4(unsigned &r0, unsigned &r1, unsigned &r2, unsigned &r3, unsigned addr) {
    asm volatile("ldmatrix.sync.aligned.m8n8.x4.shared.b16 {%0,%1,%2,%3}, [%4];"
        : "=r"(r0), "=r"(r1), "=r"(r2), "=r"(r3) : "r"(addr));
}
__device__ __forceinline__ void mma16816(float* d, const unsigned* a, unsigned b0, unsigned b1) {
    asm volatile("mma.sync.aligned.m16n8k16.row.col.f32.bf16.bf16.f32 "
        "{%0,%1,%2,%3}, {%4,%5,%6,%7}, {%8,%9}, {%0,%1,%2,%3};"
        : "+f"(d[0]), "+f"(d[1]), "+f"(d[2]), "+f"(d[3])
        : "r"(a[0]), "r"(a[1]), "r"(a[2]), "r"(a[3]), "r"(b0), "r"(b1));
}
__device__ __forceinline__ void cpasync16(unsigned dst, const void* src) {
    asm volatile("cp.async.cg.shared.global [%0], [%1], 16;" :: "r"(dst), "l"(src));
}
#define CP_COMMIT() asm volatile("cp.async.commit_group;" ::: "memory")
#define CP_WAIT1()  asm volatile("cp.async.wait_group 1;" ::: "memory")

__device__ __forceinline__ void split3(float v, __nv_bfloat16 &h, __nv_bfloat16 &m, __nv_bfloat16 &l) {
    h = __float2bfloat16(v);
    float r = v - __bfloat162float(h);
    m = __float2bfloat16(r);
    l = __float2bfloat16(r - __bfloat162float(m));
}

// ---------------- BN fold ----------------
struct FoldArgs { const float* cb[4]; const float* g[4]; const float* bt[4];
                  const float* rm[4]; const float* rv[4]; };
__global__ void fold_all_kernel(FoldArgs a)
{
    const int nchs[4] = {32, 64, 128, 256};
    int l = blockIdx.x, c = threadIdx.x;
    if (c < nchs[l]) {
        float s = a.g[l][c] / sqrtf(a.rv[l][c] + 1e-5f);
        g_scale[l*256 + c] = s;
        g_bias[l*256 + c]  = a.cb[l][c]*s + a.bt[l][c] - a.rm[l][c]*s;
    }
}

// ---------------- weight transpose (conv0 fp32) ----------------
__global__ void wt_kernel(const float* __restrict__ w, float* __restrict__ dst,
                          int cin9, int cout)
{
    int idx = blockIdx.x * 256 + threadIdx.x;
    if (idx < cin9 * cout) {
        int s  = idx / cout;
        int co = idx - s * cout;
        dst[idx] = w[(long)co * cin9 + s];
    }
}

// ---------------- weight -> bf16 split fragment layouts ----------------
__global__ void w3frag_kernel(const float* __restrict__ w3, unsigned* __restrict__ dst)
{
    int idx = blockIdx.x * 256 + threadIdx.x;
    if (idx >= 27*2*4*32*32*2) return;
    int t = idx;
    int r    = t & 1;  t >>= 1;
    int lane = t & 31; t >>= 5;
    int nt   = t & 31; t >>= 5;
    int k4   = t & 3;  t >>= 2;
    int cb   = t & 1;  t >>= 1;
    int tap  = t % 9;
    int sb   = t / 9;
    int n  = nt*8 + (lane >> 2);
    int k0 = (lane & 3)*2 + r*8;
    unsigned out = 0;
#pragma unroll
    for (int e = 0; e < 2; e++) {
        int cin = cb*64 + k4*16 + k0 + e;
        float v = w3[((long)n*128 + cin)*9 + tap];
        __nv_bfloat16 h, m, l; split3(v, h, m, l);
        __nv_bfloat16 sel = (sb == 0) ? h : (sb == 1 ? m : l);
        out |= ((unsigned)__bfloat16_as_ushort(sel)) << (16*e);
    }
    dst[idx] = out;
}

__global__ void w2frag_kernel(const float* __restrict__ w2, unsigned* __restrict__ dst)
{
    int idx = blockIdx.x * 256 + threadIdx.x;
    if (idx >= 27*4*16*32*2) return;
    int t = idx;
    int r    = t & 1;  t >>= 1;
    int lane = t & 31; t >>= 5;
    int nt   = t & 15; t >>= 4;
    int k4   = t & 3;  t >>= 2;
    int tap  = t % 9;
    int sb   = t / 9;
    int n  = nt*8 + (lane >> 2);
    int k0 = (lane & 3)*2 + r*8;
    unsigned out = 0;
#pragma unroll
    for (int e = 0; e < 2; e++) {
        int cin = k4*16 + k0 + e;
        float v = w2[((long)n*64 + cin)*9 + tap];
        __nv_bfloat16 h, m, l; split3(v, h, m, l);
        __nv_bfloat16 sel = (sb == 0) ? h : (sb == 1 ? m : l);
        out |= ((unsigned)__bfloat16_as_ushort(sel)) << (16*e);
    }
    dst[idx] = out;
}

__global__ void w1frag_kernel(const float* __restrict__ w1, unsigned* __restrict__ dst)
{
    int idx = blockIdx.x * 256 + threadIdx.x;
    if (idx >= 27*2*8*32*2) return;
    int t = idx;
    int r    = t & 1;  t >>= 1;
    int lane = t & 31; t >>= 5;
    int nt   = t & 7;  t >>= 3;
    int k4   = t & 1;  t >>= 1;
    int tap  = t % 9;
    int sb   = t / 9;
    int n  = nt*8 + (lane >> 2);
    int k0 = (lane & 3)*2 + r*8;
    unsigned out = 0;
#pragma unroll
    for (int e = 0; e < 2; e++) {
        int cin = k4*16 + k0 + e;
        float v = w1[((long)n*32 + cin)*9 + tap];
        __nv_bfloat16 h, m, l; split3(v, h, m, l);
        __nv_bfloat16 sel = (sb == 0) ? h : (sb == 1 ? m : l);
        out |= ((unsigned)__bfloat16_as_ushort(sel)) << (16*e);
    }
    dst[idx] = out;
}

// ========== X staging: 32 cin chunk, 16x16 plane (+halo), 80B pitch =========
// split planes at strides 25920 B
__device__ __forceinline__ void stageX32(char* smb, const float* inb, int tid)
{
    for (int i = tid; i < 324*16; i += 256) {
        int row = i >> 4, cp = i & 15;
        int y = row / 18, x = row - y*18;
        int gy = y - 1, gx = x - 1;
        float v0 = 0.f, v1 = 0.f;
        if ((unsigned)gy < 16u && (unsigned)gx < 16u) {
            v0 = inb[(2*cp  )*256 + gy*16 + gx];
            v1 = inb[(2*cp+1)*256 + gy*16 + gx];
        }
        __nv_bfloat16 h0, m0, l0, h1, m1, l1;
        split3(v0, h0, m0, l0); split3(v1, h1, m1, l1);
        unsigned* p0 = (unsigned*)(smb + row*80 + cp*4);
        p0[0]                             = ((unsigned)__bfloat16_as_ushort(h1) << 16) | __bfloat16_as_ushort(h0);
        *(unsigned*)((char*)p0 + 25920)   = ((unsigned)__bfloat16_as_ushort(m1) << 16) | __bfloat16_as_ushort(m0);
        *(unsigned*)((char*)p0 + 2*25920) = ((unsigned)__bfloat16_as_ushort(l1) << 16) | __bfloat16_as_ushort(l0);
    }
}

#define X1_BYTES 77760
#define W1_BYTES 12288
#define SM_MMA1  (X1_BYTES + 2*W1_BYTES)   // 102336

// ---- mainloop body: warp = M 32px (wid) x N 64, k4N k16-blocks per tap -----
template<int K4N>
__device__ __forceinline__ void mma_stepT(const char* smb, unsigned Xb, int xbytes, int wbytes,
                                          int stepbuf, int tap, int wid, int lane,
                                          unsigned xr, unsigned hs16, int splitstride,
                                          float acc[2][8][4])
{
    const ull* wS = (const ull*)(smb + xbytes + stepbuf * wbytes);
    const int dy = tap / 3, dx = tap - dy*3;
    const unsigned rowbase = (unsigned)((2*wid + dy)*18 + xr + dx);
    const int rowpitch = 80;
    for (int sa = 0; sa < 3; sa++) {
        unsigned aF[K4N][2][4];
#pragma unroll
        for (int k4 = 0; k4 < K4N; k4++)
#pragma unroll
            for (int mt = 0; mt < 2; mt++) {
                unsigned addr = Xb + (unsigned)sa*(unsigned)splitstride
                              + (rowbase + mt*18)*(unsigned)rowpitch + k4*32u + hs16;
                ldsm4(aF[k4][mt][0], aF[k4][mt][1], aF[k4][mt][2], aF[k4][mt][3], addr);
            }
        const int nsb = 3 - sa;
        for (int sb = 0; sb < nsb; sb++) {
            const ull* wSb = wS + sb*(K4N*8*32) + lane;
#pragma unroll
            for (int k4 = 0; k4 < K4N; k4++) {
#pragma unroll
                for (int nt = 0; nt < 8; nt++) {
                    ull bv = wSb[(k4*8 + nt)*32];
                    unsigned b0 = (unsigned)bv, b1 = (unsigned)(bv >> 32);
                    mma16816(acc[0][nt], aF[k4][0], b0, b1);
                    mma16816(acc[1][nt], aF[k4][1], b0, b1);
                }
            }
        }
    }
}

// ---------------- conv3: 32-cin chunks, 2 CTAs/SM ---------------------------
__global__ __launch_bounds__(256, 2)
void conv3_mma_kernel()
{
    extern __shared__ __nv_bfloat16 Xs[];
    char* smb = (char*)Xs;
    const unsigned Xb = smem_u32(Xs);
    const int tid = threadIdx.x, wid = tid >> 5, lane = tid & 31;
    const int b = blockIdx.x >> 2, nq = blockIdx.x & 3;
    const int n0 = nq * 64;

    float acc[2][8][4];
#pragma unroll
    for (int mt = 0; mt < 2; mt++)
#pragma unroll
        for (int nt = 0; nt < 8; nt++)
#pragma unroll
            for (int c = 0; c < 4; c++) acc[mt][nt][c] = 0.f;

    const unsigned xr = lane & 15;
    const unsigned hs16 = ((lane >> 4) & 1) * 16;

    // prefetch weights for step 0 (tap 0, chunk 0): 768 x 16B = 12KB
    {
        for (int j = tid; j < 768; j += 256) {
            int sb = j >> 8, rem = j & 255;
            int k4l = rem >> 7, rem2 = rem & 127;
            const ull* src = g_w3f + ((long)(sb*9 + 0)*2 + 0)*4096 + k4l*1024 + nq*256 + rem2*2;
            cpasync16(Xb + X1_BYTES + (unsigned)j*16, src);
        }
        CP_COMMIT();
    }

    for (int chunk = 0; chunk < 4; chunk++) {
        stageX32(smb, g_act2 + ((long)b*128 + chunk*32) * 256, tid);
        __syncthreads();
        for (int tap = 0; tap < 9; tap++) {
            const int step = chunk*9 + tap;
            if (step + 1 < 36) {
                const int ns = step + 1;
                const int nchunk = ns / 9, ntap = ns % 9;
                const int ncb = nchunk >> 1, nk4h = nchunk & 1;
                const unsigned wdst = Xb + X1_BYTES + (unsigned)((ns & 1) * W1_BYTES);
                for (int j = tid; j < 768; j += 256) {
                    int sb = j >> 8, rem = j & 255;
                    int k4l = rem >> 7, rem2 = rem & 127;
                    const ull* src = g_w3f + ((long)(sb*9 + ntap)*2 + ncb)*4096
                                   + (nk4h*2 + k4l)*1024 + nq*256 + rem2*2;
                    cpasync16(wdst + (unsigned)j*16, src);
                }
            }
            CP_COMMIT();
            CP_WAIT1();
            __syncthreads();
            mma_stepT<2>(smb, Xb, X1_BYTES, W1_BYTES, step & 1, tap, wid, lane, xr, hs16, 25920, acc);
            __syncthreads();
        }
    }

    // ---------- epilogue: BN + relu + maxpool2x2 + mean ----------
    float* sRed = (float*)Xs;
#pragma unroll
    for (int nt = 0; nt < 8; nt++) {
        const int co = n0 + nt*8 + (lane & 3)*2;
        const float s0c = g_scale[768 + co],     b0c = g_bias[768 + co];
        const float s1c = g_scale[768 + co + 1], b1c = g_bias[768 + co + 1];
        float q0 = fmaxf(fmaxf(fmaf(acc[0][nt][0], s0c, b0c), 0.f),
                         fmaxf(fmaf(acc[1][nt][0], s0c, b0c), 0.f));
        float q1 = fmaxf(fmaxf(fmaf(acc[0][nt][1], s1c, b1c), 0.f),
                         fmaxf(fmaf(acc[1][nt][1], s1c, b1c), 0.f));
        float q2 = fmaxf(fmaxf(fmaf(acc[0][nt][2], s0c, b0c), 0.f),
                         fmaxf(fmaf(acc[1][nt][2], s0c, b0c), 0.f));
        float q3 = fmaxf(fmaxf(fmaf(acc[0][nt][3], s1c, b1c), 0.f),
                         fmaxf(fmaf(acc[1][nt][3], s1c, b1c), 0.f));
        q0 = fmaxf(q0, __shfl_xor_sync(0xffffffffu, q0, 4));
        q1 = fmaxf(q1, __shfl_xor_sync(0xffffffffu, q1, 4));
        q2 = fmaxf(q2, __shfl_xor_sync(0xffffffffu, q2, 4));
        q3 = fmaxf(q3, __shfl_xor_sync(0xffffffffu, q3, 4));
        float s0 = q0 + q2, s1 = q1 + q3;
        s0 += __shfl_xor_sync(0xffffffffu, s0, 8);
        s0 += __shfl_xor_sync(0xffffffffu, s0, 16);
        s1 += __shfl_xor_sync(0xffffffffu, s1, 8);
        s1 += __shfl_xor_sync(0xffffffffu, s1, 16);
        if (lane < 4) {
            sRed[wid*64 + nt*8 + lane*2]     = s0;
            sRed[wid*64 + nt*8 + lane*2 + 1] = s1;
        }
    }
    __syncthreads();
    if (tid < 64) {
        float f = 0.f;
#pragma unroll
        for (int w = 0; w < 8; w++) f += sRed[w*64 + tid];
        g_feats[b*256 + n0 + tid] = f * (1.0f/64.0f);
    }
}

// ---------------- conv2: 32-cin chunks, 2 CTAs/SM ---------------------------
__global__ __launch_bounds__(256, 2)
void conv2_mma_kernel()
{
    extern __shared__ __nv_bfloat16 Xs[];
    char* smb = (char*)Xs;
    const unsigned Xb = smem_u32(Xs);
    const int tid = threadIdx.x, wid = tid >> 5, lane = tid & 31;
    const int b = blockIdx.x >> 1, nq = blockIdx.x & 1;
    const int n0 = nq * 64;

    float acc[2][8][4];
#pragma unroll
    for (int mt = 0; mt < 2; mt++)
#pragma unroll
        for (int nt = 0; nt < 8; nt++)
#pragma unroll
            for (int c = 0; c < 4; c++) acc[mt][nt][c] = 0.f;

    const unsigned xr = lane & 15;
    const unsigned hs16 = ((lane >> 4) & 1) * 16;

    {
        for (int j = tid; j < 768; j += 256) {
            int sb = j >> 8, rem = j & 255;
            int k4l = rem >> 7, rem2 = rem & 127;
            const ull* src = g_w2f + (long)(sb*9 + 0)*2048 + k4l*512 + nq*256 + rem2*2;
            cpasync16(Xb + X1_BYTES + (unsigned)j*16, src);
        }
        CP_COMMIT();
    }

    for (int chunk = 0; chunk < 2; chunk++) {
        stageX32(smb, g_act1 + ((long)b*64 + chunk*32) * 256, tid);
        __syncthreads();
        for (int tap = 0; tap < 9; tap++) {
            const int step = chunk*9 + tap;
            if (step + 1 < 18) {
                const int ns = step + 1;
                const int nchunk = ns / 9, ntap = ns % 9;
                const unsigned wdst = Xb + X1_BYTES + (unsigned)((ns & 1) * W1_BYTES);
                for (int j = tid; j < 768; j += 256) {
                    int sb = j >> 8, rem = j & 255;
                    int k4l = rem >> 7, rem2 = rem & 127;
                    const ull* src = g_w2f + (long)(sb*9 + ntap)*2048
                                   + (nchunk*2 + k4l)*512 + nq*256 + rem2*2;
                    cpasync16(wdst + (unsigned)j*16, src);
                }
            }
            CP_COMMIT();
            CP_WAIT1();
            __syncthreads();
            mma_stepT<2>(smb, Xb, X1_BYTES, W1_BYTES, step & 1, tap, wid, lane, xr, hs16, 25920, acc);
            __syncthreads();
        }
    }

    float* sOut = (float*)Xs;   // [64 co][stride 264]
#pragma unroll
    for (int nt = 0; nt < 8; nt++) {
        const int co_l = nt*8 + (lane & 3)*2;
        const int co = n0 + co_l;
        const float s0c = g_scale[512 + co],     b0c = g_bias[512 + co];
        const float s1c = g_scale[512 + co + 1], b1c = g_bias[512 + co + 1];
        const int x0 = lane >> 2;
#pragma unroll
        for (int mt = 0; mt < 2; mt++) {
            const int y = 2*wid + mt;
            float v0 = fmaxf(fmaf(acc[mt][nt][0], s0c, b0c), 0.f);
            float v1 = fmaxf(fmaf(acc[mt][nt][1], s1c, b1c), 0.f);
            float v2 = fmaxf(fmaf(acc[mt][nt][2], s0c, b0c), 0.f);
            float v3 = fmaxf(fmaf(acc[mt][nt][3], s1c, b1c), 0.f);
            sOut[(co_l  )*264 + y*16 + x0]     = v0;
            sOut[(co_l+1)*264 + y*16 + x0]     = v1;
            sOut[(co_l  )*264 + y*16 + x0 + 8] = v2;
            sOut[(co_l+1)*264 + y*16 + x0 + 8] = v3;
        }
    }
    __syncthreads();
    for (int i = tid; i < 64*256; i += 256) {
        int co = i >> 8, pix = i & 255;
        g_act2[((long)b*128 + n0 + co)*256 + pix] = sOut[co*264 + pix];
    }
}

// ---------------- conv1: mma.sync + cp.async, 2 CTAs/SM ---------------------
__global__ __launch_bounds__(256, 2)
void conv1_mma_kernel()
{
    extern __shared__ __nv_bfloat16 Xs[];
    char* smb = (char*)Xs;
    const unsigned Xb = smem_u32(Xs);
    const int tid = threadIdx.x, wid = tid >> 5, lane = tid & 31;
    const int b = blockIdx.x >> 2;
    const int tileq = blockIdx.x & 3;
    const int ty0 = (tileq >> 1) * 16, tx0 = (tileq & 1) * 16;

    float acc[2][8][4];
#pragma unroll
    for (int mt = 0; mt < 2; mt++)
#pragma unroll
        for (int nt = 0; nt < 8; nt++)
#pragma unroll
            for (int c = 0; c < 4; c++) acc[mt][nt][c] = 0.f;

    const unsigned xr = lane & 15;
    const unsigned hs16 = ((lane >> 4) & 1) * 16;

    {
        for (int j = tid; j < 768; j += 256) {
            int sb = j >> 8, rem = j & 255;
            const ull* src = g_w1f + ((long)(sb*9 + 0)*2)*256 + rem*2;
            cpasync16(Xb + X1_BYTES + (unsigned)j*16, src);
        }
        CP_COMMIT();
    }
    {
        const float* inb = g_act0 + (long)b*32*1024;
        for (int i = tid; i < 324*16; i += 256) {
            int row = i >> 4, cp = i & 15;
            int y = row / 18, x = row - y*18;
            int gy = ty0 + y - 1, gx = tx0 + x - 1;
            float v0 = 0.f, v1 = 0.f;
            if ((unsigned)gy < 32u && (unsigned)gx < 32u) {
                v0 = inb[(2*cp  )*1024 + gy*32 + gx];
                v1 = inb[(2*cp+1)*1024 + gy*32 + gx];
            }
            __nv_bfloat16 h0, m0, l0, h1, m1, l1;
            split3(v0, h0, m0, l0); split3(v1, h1, m1, l1);
            unsigned* p0 = (unsigned*)(smb + row*80 + cp*4);
            p0[0]                          = ((unsigned)__bfloat16_as_ushort(h1) << 16) | __bfloat16_as_ushort(h0);
            *(unsigned*)((char*)p0 + 25920)   = ((unsigned)__bfloat16_as_ushort(m1) << 16) | __bfloat16_as_ushort(m0);
            *(unsigned*)((char*)p0 + 2*25920) = ((unsigned)__bfloat16_as_ushort(l1) << 16) | __bfloat16_as_ushort(l0);
        }
    }
    __syncthreads();

    for (int step = 0; step < 9; step++) {
        if (step + 1 < 9) {
            const unsigned wdst = Xb + X1_BYTES + (unsigned)(((step+1) & 1) * W1_BYTES);
            const int ntap = step + 1;
            for (int j = tid; j < 768; j += 256) {
                int sb = j >> 8, rem = j & 255;
                const ull* src = g_w1f + ((long)(sb*9 + ntap)*2)*256 + rem*2;
                cpasync16(wdst + (unsigned)j*16, src);
            }
        }
        CP_COMMIT();
        CP_WAIT1();
        __syncthreads();
        mma_stepT<2>(smb, Xb, X1_BYTES, W1_BYTES, step & 1, step, wid, lane, xr, hs16, 25920, acc);
        __syncthreads();
    }

    // ---------- epilogue: BN + relu + maxpool2x2, store to g_act1 ----------
    float* sOut = (float*)Xs;   // [64 co][stride 68]
#pragma unroll
    for (int nt = 0; nt < 8; nt++) {
        const int co_l = nt*8 + (lane & 3)*2;
        const int co = co_l;
        const float s0c = g_scale[256 + co],     b0c = g_bias[256 + co];
        const float s1c = g_scale[256 + co + 1], b1c = g_bias[256 + co + 1];
        float q0 = fmaxf(fmaxf(fmaf(acc[0][nt][0], s0c, b0c), 0.f),
                         fmaxf(fmaf(acc[1][nt][0], s0c, b0c), 0.f));
        float q1 = fmaxf(fmaxf(fmaf(acc[0][nt][1], s1c, b1c), 0.f),
                         fmaxf(fmaf(acc[1][nt][1], s1c, b1c), 0.f));
        float q2 = fmaxf(fmaxf(fmaf(acc[0][nt][2], s0c, b0c), 0.f),
                         fmaxf(fmaf(acc[1][nt][2], s0c, b0c), 0.f));
        float q3 = fmaxf(fmaxf(fmaf(acc[0][nt][3], s1c, b1c), 0.f),
                         fmaxf(fmaf(acc[1][nt][3], s1c, b1c), 0.f));
        q0 = fmaxf(q0, __shfl_xor_sync(0xffffffffu, q0, 4));
        q1 = fmaxf(q1, __shfl_xor_sync(0xffffffffu, q1, 4));
        q2 = fmaxf(q2, __shfl_xor_sync(0xffffffffu, q2, 4));
        q3 = fmaxf(q3, __shfl_xor_sync(0xffffffffu, q3, 4));
        if (((lane >> 2) & 1) == 0) {
            const int px0 = (lane >> 2) >> 1;
            sOut[(co_l  )*68 + wid*8 + px0]     = q0;
            sOut[(co_l+1)*68 + wid*8 + px0]     = q1;
            sOut[(co_l  )*68 + wid*8 + px0 + 4] = q2;
            sOut[(co_l+1)*68 + wid*8 + px0 + 4] = q3;
        }
    }
    __syncthreads();
    {
        const int oy0 = ty0 >> 1, ox0 = tx0 >> 1;
        for (int i = tid; i < 64*64; i += 256) {
            int co = i >> 6, p = i & 63;
            int Y = p >> 3, X = p & 7;
            g_act1[((long)b*64 + co)*256 + (oy0 + Y)*16 + (ox0 + X)] = sOut[co*68 + p];
        }
    }
}

// ---------------- conv0 fp32 ----------------
__global__ __launch_bounds__(256, 2)
void conv0_kernel(const float* __restrict__ x, const float* __restrict__ wT)
{
    const int CIN = 3, COUT = 32, H = 32;
    const int b   = blockIdx.z;
    const int tyi = blockIdx.y / 2, txi = blockIdx.y % 2;
    const int ty0 = tyi * 16, tx0 = txi * 16;

    const int tid = threadIdx.x;
    const int cg  = tid >> 6;
    const int p   = tid & 63;
    const int py  = p >> 3, px = p & 7;
    const int oy  = 2*py,  ox = 2*px;

    extern __shared__ ull sIn2[];

    ull acc2[4][4];
#pragma unroll
    for (int i = 0; i < 4; i++)
#pragma unroll
        for (int k = 0; k < 4; k++) acc2[i][k] = 0ull;

    const int co0 = cg*8;

    const float* inb = x + (long)b*CIN*H*H;
    for (int i = tid; i < CIN*324; i += 256) {
        int c = i / 324; int r = i - c*324;
        int y = r / 18,  xx = r - y*18;
        int gy = ty0 + y - 1, gx = tx0 + xx - 1;
        float v = 0.f;
        if ((unsigned)gy < (unsigned)H && (unsigned)gx < (unsigned)H)
            v = inb[(long)c*H*H + gy*H + gx];
        sIn2[c*360 + y*20 + xx] = bcast2(v);
    }
    __syncthreads();

#pragma unroll
    for (int c = 0; c < CIN; c++) {
        const ull* sic = sIn2 + c*360 + oy*20 + ox;
        ull iv[4][4];
#pragma unroll
        for (int dy = 0; dy < 4; dy++) {
            ulonglong2 a0 = *(const ulonglong2*)(sic + dy*20);
            ulonglong2 a1 = *(const ulonglong2*)(sic + dy*20 + 2);
            iv[dy][0] = a0.x; iv[dy][1] = a0.y;
            iv[dy][2] = a1.x; iv[dy][3] = a1.y;
        }
        const float* wr = wT + (long)c*9*COUT + co0;
#pragma unroll
        for (int t = 0; t < 9; t++) {
            ulonglong2 w01 = __ldg((const ulonglong2*)(wr + t*COUT));
            ulonglong2 w23 = __ldg((const ulonglong2*)(wr + t*COUT + 4));
            const int dy = t / 3, dx = t % 3;
            ffma2(acc2[0][0], iv[dy  ][dx  ], w01.x);
            ffma2(acc2[0][1], iv[dy  ][dx  ], w01.y);
            ffma2(acc2[0][2], iv[dy  ][dx  ], w23.x);
            ffma2(acc2[0][3], iv[dy  ][dx  ], w23.y);
            ffma2(acc2[1][0], iv[dy  ][dx+1], w01.x);
            ffma2(acc2[1][1], iv[dy  ][dx+1], w01.y);
            ffma2(acc2[1][2], iv[dy  ][dx+1], w23.x);
            ffma2(acc2[1][3], iv[dy  ][dx+1], w23.y);
            ffma2(acc2[2][0], iv[dy+1][dx  ], w01.x);
            ffma2(acc2[2][1], iv[dy+1][dx  ], w01.y);
            ffma2(acc2[2][2], iv[dy+1][dx  ], w23.x);
            ffma2(acc2[2][3], iv[dy+1][dx  ], w23.y);
            ffma2(acc2[3][0], iv[dy+1][dx+1], w01.x);
            ffma2(acc2[3][1], iv[dy+1][dx+1], w01.y);
            ffma2(acc2[3][2], iv[dy+1][dx+1], w23.x);
            ffma2(acc2[3][3], iv[dy+1][dx+1], w23.y);
        }
    }

    float acc[4][8];
#pragma unroll
    for (int i = 0; i < 4; i++)
#pragma unroll
        for (int kk = 0; kk < 4; kk++)
            unpack2(acc[i][2*kk], acc[i][2*kk+1], acc2[i][kk]);

#pragma unroll
    for (int k = 0; k < 8; k++) {
        const float s  = g_scale[co0 + k];
        const float bi = g_bias [co0 + k];
#pragma unroll
        for (int r = 0; r < 2; r++)
#pragma unroll
            for (int s2 = 0; s2 < 2; s2++) {
                float v = fmaxf(fmaf(acc[r*2+s2][k], s, bi), 0.f);
                g_act0[(((long)b*32 + co0 + k)*H + (ty0+oy+r))*H + (tx0+ox+s2)] = v;
            }
    }
}

// ---------------- classifier + log_softmax + conf ----------------
__global__ void classifier_kernel(const float* __restrict__ cls_w,
                                  const float* __restrict__ cls_b)
{
    const int b = blockIdx.x;
    const int tid = threadIdx.x;   // 128
    __shared__ float sf[256];
    __shared__ float sl[80];
    for (int i = tid; i < 256; i += 128) sf[i] = g_feats[b*256 + i];
    __syncthreads();
    if (tid < 80) {
        const float* wr = cls_w + (long)tid * 256;
        float s = 0.f;
#pragma unroll 8
        for (int k = 0; k < 256; k++) s = fmaf(sf[k], wr[k], s);
        s += cls_b[tid];
        sl[tid] = s;
        g_logits[(long)b*80 + tid] = s;
    }
    __syncthreads();
    if (tid < 8) {
        float m = -1e30f;
        for (int c = 0; c < 10; c++) m = fmaxf(m, sl[tid*10 + c]);
        float se = 0.f;
        for (int c = 0; c < 10; c++) se += expf(sl[tid*10 + c] - m);
        float lse = m + logf(se);
        float cf = 0.f;
        for (int c = 0; c < 10; c++) {
            float lp = sl[tid*10 + c] - lse;
            cf += expf(lp) * lp;
        }
        g_conf[b*8 + tid] = cf;
    }
}

// ---------------- greedy capacity router ----------------
__global__ __launch_bounds__(1024)
void route_kernel()
{
    __shared__ unsigned long long keys[4096];
    __shared__ unsigned char D[4096];
    __shared__ unsigned char sc[512];
    __shared__ int ec[8];
    __shared__ int assigned;

    const int tid = threadIdx.x;
    for (int i = tid; i < 4096; i += 1024) D[i] = 0;
    if (tid < 512) sc[tid] = 0;
    if (tid < 8)   ec[tid] = 0;
    if (tid == 0)  assigned = 0;
    __syncthreads();

    for (int cyc_i = 0; cyc_i < 4; cyc_i++) {
        for (int i = tid; i < 4096; i += 1024) {
            float v = g_conf[i];
            if (cyc_i > 0) v = v * (1.0f - (float)ec[i & 7] / 160.0f);
            unsigned int fb = __float_as_uint(v);
            unsigned int ou = (fb & 0x80000000u) ? ~fb : (fb | 0x80000000u);
            keys[i] = ((unsigned long long)(~ou) << 32) | (unsigned int)i;
        }
        __syncthreads();
        for (int k2 = 2; k2 <= 4096; k2 <<= 1) {
            for (int j = k2 >> 1; j > 0; j >>= 1) {
                for (int i = tid; i < 4096; i += 1024) {
                    int ixj = i ^ j;
                    if (ixj > i) {
                        unsigned long long a = keys[i], bb = keys[ixj];
                        bool up = ((i & k2) == 0);
                        if ((a > bb) == up) { keys[i] = bb; keys[ixj] = a; }
                    }
                }
                __syncthreads();
            }
        }
        if (tid == 0) {
            int cyc = 0, asg = assigned;
            for (int s = 0; s < 4096; s++) {
                if (cyc >= 256 || asg >= 1024) break;
                int id = (int)(keys[s] & 0xFFFFFFFFull);
                int jj = id & 7, bb = id >> 3;
                if (!D[id] && ec[jj] < 160 && sc[bb] < 2) {
                    D[id] = 1; ec[jj]++; sc[bb]++; asg++; cyc++;
                }
            }
            assigned = asg;
        }
        __syncthreads();
    }
    for (int i = tid; i < 4096; i += 1024) g_D[i] = (int)D[i];
}

// ---------------- final combine ----------------
__global__ void final_kernel(float* __restrict__ out, int out_size)
{
    const int b = blockIdx.x;
    const int lane = threadIdx.x;
    int nd = 0;
#pragma unroll
    for (int e = 0; e < 8; e++) nd += g_D[b*8 + e];
    float norm = fmaxf((float)nd, 1.0f);
    if (lane < 10) {
        float s = 0.f;
#pragma unroll
        for (int e = 0; e < 8; e++) {
            if (g_D[b*8 + e])
                s += g_conf[b*8 + e] * g_logits[(long)(b*8 + e)*10 + lane];
        }
        out[b*10 + lane] = s / norm;
    }
    if (out_size >= 5120 + 4096 && lane < 8)
        out[5120 + b*8 + lane] = g_conf[b*8 + lane];
    if (out_size >= 5120 + 8192 && lane < 8)
        out[5120 + 4096 + b*8 + lane] = g_D[b*8 + lane] ? 1.0f : 0.0f;
}

// ---------------- launch ----------------
extern "C" void kernel_launch(void* const* d_in, const int* in_sizes, int n_in,
                              void* d_out, int out_size)
{
    const float* x = (const float*)d_in[0];
    FoldArgs fa;
    const float* w[4];
    for (int i = 0; i < 4; i++) {
        w [i]    = (const float*)d_in[1 + i*6 + 0];
        fa.cb[i] = (const float*)d_in[1 + i*6 + 1];
        fa.g [i] = (const float*)d_in[1 + i*6 + 2];
        fa.bt[i] = (const float*)d_in[1 + i*6 + 3];
        fa.rm[i] = (const float*)d_in[1 + i*6 + 4];
        fa.rv[i] = (const float*)d_in[1 + i*6 + 5];
    }
    const float* cls_w = (const float*)d_in[25];
    const float* cls_b = (const float*)d_in[26];

    const int SM3 = 3 * 360 * 8;
    cudaFuncSetAttribute(conv1_mma_kernel, cudaFuncAttributeMaxDynamicSharedMemorySize, SM_MMA1);
    cudaFuncSetAttribute(conv2_mma_kernel, cudaFuncAttributeMaxDynamicSharedMemorySize, SM_MMA1);
    cudaFuncSetAttribute(conv3_mma_kernel, cudaFuncAttributeMaxDynamicSharedMemorySize, SM_MMA1);

    fold_all_kernel<<<4, 256>>>(fa);

    float* wT0; unsigned* w3f; unsigned* w2f; unsigned* w1f;
    cudaGetSymbolAddress((void**)&wT0, g_wT0);
    cudaGetSymbolAddress((void**)&w3f, g_w3f);
    cudaGetSymbolAddress((void**)&w2f, g_w2f);
    cudaGetSymbolAddress((void**)&w1f, g_w1f);
    wt_kernel<<<(27*32 + 255)/256, 256>>>(w[0], wT0, 27, 32);
    w1frag_kernel<<<(27*2*8*32*2    + 255)/256, 256>>>(w[1], w1f);
    w2frag_kernel<<<(27*4*16*32*2   + 255)/256, 256>>>(w[2], w2f);
    w3frag_kernel<<<(27*2*4*32*32*2 + 255)/256, 256>>>(w[3], w3f);

    conv0_kernel<<<dim3(1,4,512), 256, SM3>>>(x, wT0);
    conv1_mma_kernel<<<2048, 256, SM_MMA1>>>();
    conv2_mma_kernel<<<1024, 256, SM_MMA1>>>();
    conv3_mma_kernel<<<2048, 256, SM_MMA1>>>();

    classifier_kernel<<<512, 128>>>(cls_w, cls_b);
    route_kernel<<<1, 1024>>>();
    final_kernel<<<512, 32>>>((float*)d_out, out_size);
}

// round 13
// speedup vs baseline: 1.1919x; 1.1107x over previous
#include <cuda_runtime.h>
#include <cuda_bf16.h>
#include <math.h>

typedef unsigned long long ull;

// ---------------- device scratch ----------------
__device__ float g_act0[512*32*32*32];
__device__ float g_act1[512*64*16*16];
__device__ float g_act2[512*128*16*16];
__device__ float g_feats[512*256];
__device__ float g_logits[512*8*10];
__device__ float g_conf[512*8];
__device__ float g_scale[4*256];
__device__ float g_bias[4*256];
__device__ float g_wT0[27*32];
__device__ ull g_w3f[27*2*4*32*32];
__device__ ull g_w2f[27*4*16*32];
__device__ ull g_w1f[27*2*8*32];

// ---------------- packed f32x2 helpers ----------------
__device__ __forceinline__ void ffma2(ull &d, ull a, ull b) {
    asm("fma.rn.f32x2 %0, %1, %2, %0;" : "+l"(d) : "l"(a), "l"(b));
}
__device__ __forceinline__ ull bcast2(float v) {
    ull r; unsigned int u = __float_as_uint(v);
    asm("mov.b64 %0, {%1, %1};" : "=l"(r) : "r"(u));
    return r;
}
__device__ __forceinline__ void unpack2(float &lo, float &hi, ull v) {
    unsigned int l, h;
    asm("mov.b64 {%0, %1}, %2;" : "=r"(l), "=r"(h) : "l"(v));
    lo = __uint_as_float(l); hi = __uint_as_float(h);
}

// ---------------- mma helpers ----------------
__device__ __forceinline__ unsigned smem_u32(const void* p) {
    unsigned a;
    asm("{ .reg .u64 t; cvta.to.shared.u64 t, %1; cvt.u32.u64 %0, t; }" : "=r"(a) : "l"(p));
    return a;
}
__device__ __forceinline__ void ldsm4(unsigned &r0, unsigned &r1, unsigned &r2, unsigned &r3, unsigned addr) {
    asm volatile("ldmatrix.sync.aligned.m8n8.x4.shared.b16 {%0,%1,%2,%3}, [%4];"
        : "=r"(r0), "=r"(r1), "=r"(r2), "=r"(r3) : "r"(addr));
}
__device__ __forceinline__ void mma16816(float* d, const unsigned* a, unsigned b0, unsigned b1) {
    asm volatile("mma.sync.aligned.m16n8k16.row.col.f32.bf16.bf16.f32 "
        "{%0,%1,%2,%3}, {%4,%5,%6,%7}, {%8,%9}, {%0,%1,%2,%3};"
        : "+f"(d[0]), "+f"(d[1]), "+f"(d[2]), "+f"(d[3])
        : "r"(a[0]), "r"(a[1]), "r"(a[2]), "r"(a[3]), "r"(b0), "r"(b1));
}
__device__ __forceinline__ void cpasync16(unsigned dst, const void* src) {
    asm volatile("cp.async.cg.shared.global [%0], [%1], 16;" :: "r"(dst), "l"(src));
}
#define CP_COMMIT() asm volatile("cp.async.commit_group;" ::: "memory")
#define CP_WAIT1()  asm volatile("cp.async.wait_group 1;" ::: "memory")

__device__ __forceinline__ void split3(float v, __nv_bfloat16 &h, __nv_bfloat16 &m, __nv_bfloat16 &l) {
    h = __float2bfloat16(v);
    float r = v - __bfloat162float(h);
    m = __float2bfloat16(r);
    l = __float2bfloat16(r - __bfloat162float(m));
}

// ---------------- BN fold ----------------
struct FoldArgs { const float* cb[4]; const float* g[4]; const float* bt[4];
                  const float* rm[4]; const float* rv[4]; };
__global__ void fold_all_kernel(FoldArgs a)
{
    const int nchs[4] = {32, 64, 128, 256};
    int l = blockIdx.x, c = threadIdx.x;
    if (c < nchs[l]) {
        float s = a.g[l][c] / sqrtf(a.rv[l][c] + 1e-5f);
        g_scale[l*256 + c] = s;
        g_bias[l*256 + c]  = a.cb[l][c]*s + a.bt[l][c] - a.rm[l][c]*s;
    }
}

// ---------------- weight transpose (conv0 fp32) ----------------
__global__ void wt_kernel(const float* __restrict__ w, float* __restrict__ dst,
                          int cin9, int cout)
{
    int idx = blockIdx.x * 256 + threadIdx.x;
    if (idx < cin9 * cout) {
        int s  = idx / cout;
        int co = idx - s * cout;
        dst[idx] = w[(long)co * cin9 + s];
    }
}

// ---------------- weight -> bf16 split fragment layouts ----------------
__global__ void w3frag_kernel(const float* __restrict__ w3, unsigned* __restrict__ dst)
{
    int idx = blockIdx.x * 256 + threadIdx.x;
    if (idx >= 27*2*4*32*32*2) return;
    int t = idx;
    int r    = t & 1;  t >>= 1;
    int lane = t & 31; t >>= 5;
    int nt   = t & 31; t >>= 5;
    int k4   = t & 3;  t >>= 2;
    int cb   = t & 1;  t >>= 1;
    int tap  = t % 9;
    int sb   = t / 9;
    int n  = nt*8 + (lane >> 2);
    int k0 = (lane & 3)*2 + r*8;
    unsigned out = 0;
#pragma unroll
    for (int e = 0; e < 2; e++) {
        int cin = cb*64 + k4*16 + k0 + e;
        float v = w3[((long)n*128 + cin)*9 + tap];
        __nv_bfloat16 h, m, l; split3(v, h, m, l);
        __nv_bfloat16 sel = (sb == 0) ? h : (sb == 1 ? m : l);
        out |= ((unsigned)__bfloat16_as_ushort(sel)) << (16*e);
    }
    dst[idx] = out;
}

__global__ void w2frag_kernel(const float* __restrict__ w2, unsigned* __restrict__ dst)
{
    int idx = blockIdx.x * 256 + threadIdx.x;
    if (idx >= 27*4*16*32*2) return;
    int t = idx;
    int r    = t & 1;  t >>= 1;
    int lane = t & 31; t >>= 5;
    int nt   = t & 15; t >>= 4;
    int k4   = t & 3;  t >>= 2;
    int tap  = t % 9;
    int sb   = t / 9;
    int n  = nt*8 + (lane >> 2);
    int k0 = (lane & 3)*2 + r*8;
    unsigned out = 0;
#pragma unroll
    for (int e = 0; e < 2; e++) {
        int cin = k4*16 + k0 + e;
        float v = w2[((long)n*64 + cin)*9 + tap];
        __nv_bfloat16 h, m, l; split3(v, h, m, l);
        __nv_bfloat16 sel = (sb == 0) ? h : (sb == 1 ? m : l);
        out |= ((unsigned)__bfloat16_as_ushort(sel)) << (16*e);
    }
    dst[idx] = out;
}

__global__ void w1frag_kernel(const float* __restrict__ w1, unsigned* __restrict__ dst)
{
    int idx = blockIdx.x * 256 + threadIdx.x;
    if (idx >= 27*2*8*32*2) return;
    int t = idx;
    int r    = t & 1;  t >>= 1;
    int lane = t & 31; t >>= 5;
    int nt   = t & 7;  t >>= 3;
    int k4   = t & 1;  t >>= 1;
    int tap  = t % 9;
    int sb   = t / 9;
    int n  = nt*8 + (lane >> 2);
    int k0 = (lane & 3)*2 + r*8;
    unsigned out = 0;
#pragma unroll
    for (int e = 0; e < 2; e++) {
        int cin = k4*16 + k0 + e;
        float v = w1[((long)n*32 + cin)*9 + tap];
        __nv_bfloat16 h, m, l; split3(v, h, m, l);
        __nv_bfloat16 sel = (sb == 0) ? h : (sb == 1 ? m : l);
        out |= ((unsigned)__bfloat16_as_ushort(sel)) << (16*e);
    }
    dst[idx] = out;
}

// ========== X staging: 32 cin chunk, 16x16 plane (+halo), 80B pitch =========
__device__ __forceinline__ void stageX32(char* smb, const float* inb, int tid)
{
    for (int i = tid; i < 324*16; i += 256) {
        int row = i >> 4, cp = i & 15;
        int y = row / 18, x = row - y*18;
        int gy = y - 1, gx = x - 1;
        float v0 = 0.f, v1 = 0.f;
        if ((unsigned)gy < 16u && (unsigned)gx < 16u) {
            v0 = inb[(2*cp  )*256 + gy*16 + gx];
            v1 = inb[(2*cp+1)*256 + gy*16 + gx];
        }
        __nv_bfloat16 h0, m0, l0, h1, m1, l1;
        split3(v0, h0, m0, l0); split3(v1, h1, m1, l1);
        unsigned* p0 = (unsigned*)(smb + row*80 + cp*4);
        p0[0]                             = ((unsigned)__bfloat16_as_ushort(h1) << 16) | __bfloat16_as_ushort(h0);
        *(unsigned*)((char*)p0 + 25920)   = ((unsigned)__bfloat16_as_ushort(m1) << 16) | __bfloat16_as_ushort(m0);
        *(unsigned*)((char*)p0 + 2*25920) = ((unsigned)__bfloat16_as_ushort(l1) << 16) | __bfloat16_as_ushort(l0);
    }
}

#define X1_BYTES 77760
#define W1_BYTES 12288
#define SM_MMA1  (X1_BYTES + 2*W1_BYTES)   // 102336

// ---- mainloop body: warp = M 32px (wid) x N 64, k4N k16-blocks per tap -----
template<int K4N>
__device__ __forceinline__ void mma_stepT(const char* smb, unsigned Xb, int xbytes, int wbytes,
                                          int stepbuf, int tap, int wid, int lane,
                                          unsigned xr, unsigned hs16, int splitstride,
                                          float acc[2][8][4])
{
    const ull* wS = (const ull*)(smb + xbytes + stepbuf * wbytes);
    const int dy = tap / 3, dx = tap - dy*3;
    const unsigned rowbase = (unsigned)((2*wid + dy)*18 + xr + dx);
    const int rowpitch = 80;
    for (int sa = 0; sa < 3; sa++) {
        unsigned aF[K4N][2][4];
#pragma unroll
        for (int k4 = 0; k4 < K4N; k4++)
#pragma unroll
            for (int mt = 0; mt < 2; mt++) {
                unsigned addr = Xb + (unsigned)sa*(unsigned)splitstride
                              + (rowbase + mt*18)*(unsigned)rowpitch + k4*32u + hs16;
                ldsm4(aF[k4][mt][0], aF[k4][mt][1], aF[k4][mt][2], aF[k4][mt][3], addr);
            }
        const int nsb = 3 - sa;
        for (int sb = 0; sb < nsb; sb++) {
            const ull* wSb = wS + sb*(K4N*8*32) + lane;
#pragma unroll
            for (int k4 = 0; k4 < K4N; k4++) {
#pragma unroll
                for (int nt = 0; nt < 8; nt++) {
                    ull bv = wSb[(k4*8 + nt)*32];
                    unsigned b0 = (unsigned)bv, b1 = (unsigned)(bv >> 32);
                    mma16816(acc[0][nt], aF[k4][0], b0, b1);
                    mma16816(acc[1][nt], aF[k4][1], b0, b1);
                }
            }
        }
    }
}

// ---------------- conv3 ----------------
__global__ __launch_bounds__(256, 2)
void conv3_mma_kernel()
{
    extern __shared__ __nv_bfloat16 Xs[];
    char* smb = (char*)Xs;
    const unsigned Xb = smem_u32(Xs);
    const int tid = threadIdx.x, wid = tid >> 5, lane = tid & 31;
    const int b = blockIdx.x >> 2, nq = blockIdx.x & 3;
    const int n0 = nq * 64;

    float acc[2][8][4];
#pragma unroll
    for (int mt = 0; mt < 2; mt++)
#pragma unroll
        for (int nt = 0; nt < 8; nt++)
#pragma unroll
            for (int c = 0; c < 4; c++) acc[mt][nt][c] = 0.f;

    const unsigned xr = lane & 15;
    const unsigned hs16 = ((lane >> 4) & 1) * 16;

    {
        for (int j = tid; j < 768; j += 256) {
            int sb = j >> 8, rem = j & 255;
            int k4l = rem >> 7, rem2 = rem & 127;
            const ull* src = g_w3f + ((long)(sb*9 + 0)*2 + 0)*4096 + k4l*1024 + nq*256 + rem2*2;
            cpasync16(Xb + X1_BYTES + (unsigned)j*16, src);
        }
        CP_COMMIT();
    }

    for (int chunk = 0; chunk < 4; chunk++) {
        stageX32(smb, g_act2 + ((long)b*128 + chunk*32) * 256, tid);
        __syncthreads();
        for (int tap = 0; tap < 9; tap++) {
            const int step = chunk*9 + tap;
            if (step + 1 < 36) {
                const int ns = step + 1;
                const int nchunk = ns / 9, ntap = ns % 9;
                const int ncb = nchunk >> 1, nk4h = nchunk & 1;
                const unsigned wdst = Xb + X1_BYTES + (unsigned)((ns & 1) * W1_BYTES);
                for (int j = tid; j < 768; j += 256) {
                    int sb = j >> 8, rem = j & 255;
                    int k4l = rem >> 7, rem2 = rem & 127;
                    const ull* src = g_w3f + ((long)(sb*9 + ntap)*2 + ncb)*4096
                                   + (nk4h*2 + k4l)*1024 + nq*256 + rem2*2;
                    cpasync16(wdst + (unsigned)j*16, src);
                }
            }
            CP_COMMIT();
            CP_WAIT1();
            __syncthreads();
            mma_stepT<2>(smb, Xb, X1_BYTES, W1_BYTES, step & 1, tap, wid, lane, xr, hs16, 25920, acc);
            __syncthreads();
        }
    }

    float* sRed = (float*)Xs;
#pragma unroll
    for (int nt = 0; nt < 8; nt++) {
        const int co = n0 + nt*8 + (lane & 3)*2;
        const float s0c = g_scale[768 + co],     b0c = g_bias[768 + co];
        const float s1c = g_scale[768 + co + 1], b1c = g_bias[768 + co + 1];
        float q0 = fmaxf(fmaxf(fmaf(acc[0][nt][0], s0c, b0c), 0.f),
                         fmaxf(fmaf(acc[1][nt][0], s0c, b0c), 0.f));
        float q1 = fmaxf(fmaxf(fmaf(acc[0][nt][1], s1c, b1c), 0.f),
                         fmaxf(fmaf(acc[1][nt][1], s1c, b1c), 0.f));
        float q2 = fmaxf(fmaxf(fmaf(acc[0][nt][2], s0c, b0c), 0.f),
                         fmaxf(fmaf(acc[1][nt][2], s0c, b0c), 0.f));
        float q3 = fmaxf(fmaxf(fmaf(acc[0][nt][3], s1c, b1c), 0.f),
                         fmaxf(fmaf(acc[1][nt][3], s1c, b1c), 0.f));
        q0 = fmaxf(q0, __shfl_xor_sync(0xffffffffu, q0, 4));
        q1 = fmaxf(q1, __shfl_xor_sync(0xffffffffu, q1, 4));
        q2 = fmaxf(q2, __shfl_xor_sync(0xffffffffu, q2, 4));
        q3 = fmaxf(q3, __shfl_xor_sync(0xffffffffu, q3, 4));
        float s0 = q0 + q2, s1 = q1 + q3;
        s0 += __shfl_xor_sync(0xffffffffu, s0, 8);
        s0 += __shfl_xor_sync(0xffffffffu, s0, 16);
        s1 += __shfl_xor_sync(0xffffffffu, s1, 8);
        s1 += __shfl_xor_sync(0xffffffffu, s1, 16);
        if (lane < 4) {
            sRed[wid*64 + nt*8 + lane*2]     = s0;
            sRed[wid*64 + nt*8 + lane*2 + 1] = s1;
        }
    }
    __syncthreads();
    if (tid < 64) {
        float f = 0.f;
#pragma unroll
        for (int w = 0; w < 8; w++) f += sRed[w*64 + tid];
        g_feats[b*256 + n0 + tid] = f * (1.0f/64.0f);
    }
}

// ---------------- conv2 ----------------
__global__ __launch_bounds__(256, 2)
void conv2_mma_kernel()
{
    extern __shared__ __nv_bfloat16 Xs[];
    char* smb = (char*)Xs;
    const unsigned Xb = smem_u32(Xs);
    const int tid = threadIdx.x, wid = tid >> 5, lane = tid & 31;
    const int b = blockIdx.x >> 1, nq = blockIdx.x & 1;
    const int n0 = nq * 64;

    float acc[2][8][4];
#pragma unroll
    for (int mt = 0; mt < 2; mt++)
#pragma unroll
        for (int nt = 0; nt < 8; nt++)
#pragma unroll
            for (int c = 0; c < 4; c++) acc[mt][nt][c] = 0.f;

    const unsigned xr = lane & 15;
    const unsigned hs16 = ((lane >> 4) & 1) * 16;

    {
        for (int j = tid; j < 768; j += 256) {
            int sb = j >> 8, rem = j & 255;
            int k4l = rem >> 7, rem2 = rem & 127;
            const ull* src = g_w2f + (long)(sb*9 + 0)*2048 + k4l*512 + nq*256 + rem2*2;
            cpasync16(Xb + X1_BYTES + (unsigned)j*16, src);
        }
        CP_COMMIT();
    }

    for (int chunk = 0; chunk < 2; chunk++) {
        stageX32(smb, g_act1 + ((long)b*64 + chunk*32) * 256, tid);
        __syncthreads();
        for (int tap = 0; tap < 9; tap++) {
            const int step = chunk*9 + tap;
            if (step + 1 < 18) {
                const int ns = step + 1;
                const int nchunk = ns / 9, ntap = ns % 9;
                const unsigned wdst = Xb + X1_BYTES + (unsigned)((ns & 1) * W1_BYTES);
                for (int j = tid; j < 768; j += 256) {
                    int sb = j >> 8, rem = j & 255;
                    int k4l = rem >> 7, rem2 = rem & 127;
                    const ull* src = g_w2f + (long)(sb*9 + ntap)*2048
                                   + (nchunk*2 + k4l)*512 + nq*256 + rem2*2;
                    cpasync16(wdst + (unsigned)j*16, src);
                }
            }
            CP_COMMIT();
            CP_WAIT1();
            __syncthreads();
            mma_stepT<2>(smb, Xb, X1_BYTES, W1_BYTES, step & 1, tap, wid, lane, xr, hs16, 25920, acc);
            __syncthreads();
        }
    }

    float* sOut = (float*)Xs;
#pragma unroll
    for (int nt = 0; nt < 8; nt++) {
        const int co_l = nt*8 + (lane & 3)*2;
        const int co = n0 + co_l;
        const float s0c = g_scale[512 + co],     b0c = g_bias[512 + co];
        const float s1c = g_scale[512 + co + 1], b1c = g_bias[512 + co + 1];
        const int x0 = lane >> 2;
#pragma unroll
        for (int mt = 0; mt < 2; mt++) {
            const int y = 2*wid + mt;
            float v0 = fmaxf(fmaf(acc[mt][nt][0], s0c, b0c), 0.f);
            float v1 = fmaxf(fmaf(acc[mt][nt][1], s1c, b1c), 0.f);
            float v2 = fmaxf(fmaf(acc[mt][nt][2], s0c, b0c), 0.f);
            float v3 = fmaxf(fmaf(acc[mt][nt][3], s1c, b1c), 0.f);
            sOut[(co_l  )*264 + y*16 + x0]     = v0;
            sOut[(co_l+1)*264 + y*16 + x0]     = v1;
            sOut[(co_l  )*264 + y*16 + x0 + 8] = v2;
            sOut[(co_l+1)*264 + y*16 + x0 + 8] = v3;
        }
    }
    __syncthreads();
    for (int i = tid; i < 64*256; i += 256) {
        int co = i >> 8, pix = i & 255;
        g_act2[((long)b*128 + n0 + co)*256 + pix] = sOut[co*264 + pix];
    }
}

// ---------------- conv1 ----------------
__global__ __launch_bounds__(256, 2)
void conv1_mma_kernel()
{
    extern __shared__ __nv_bfloat16 Xs[];
    char* smb = (char*)Xs;
    const unsigned Xb = smem_u32(Xs);
    const int tid = threadIdx.x, wid = tid >> 5, lane = tid & 31;
    const int b = blockIdx.x >> 2;
    const int tileq = blockIdx.x & 3;
    const int ty0 = (tileq >> 1) * 16, tx0 = (tileq & 1) * 16;

    float acc[2][8][4];
#pragma unroll
    for (int mt = 0; mt < 2; mt++)
#pragma unroll
        for (int nt = 0; nt < 8; nt++)
#pragma unroll
            for (int c = 0; c < 4; c++) acc[mt][nt][c] = 0.f;

    const unsigned xr = lane & 15;
    const unsigned hs16 = ((lane >> 4) & 1) * 16;

    {
        for (int j = tid; j < 768; j += 256) {
            int sb = j >> 8, rem = j & 255;
            const ull* src = g_w1f + ((long)(sb*9 + 0)*2)*256 + rem*2;
            cpasync16(Xb + X1_BYTES + (unsigned)j*16, src);
        }
        CP_COMMIT();
    }
    {
        const float* inb = g_act0 + (long)b*32*1024;
        for (int i = tid; i < 324*16; i += 256) {
            int row = i >> 4, cp = i & 15;
            int y = row / 18, x = row - y*18;
            int gy = ty0 + y - 1, gx = tx0 + x - 1;
            float v0 = 0.f, v1 = 0.f;
            if ((unsigned)gy < 32u && (unsigned)gx < 32u) {
                v0 = inb[(2*cp  )*1024 + gy*32 + gx];
                v1 = inb[(2*cp+1)*1024 + gy*32 + gx];
            }
            __nv_bfloat16 h0, m0, l0, h1, m1, l1;
            split3(v0, h0, m0, l0); split3(v1, h1, m1, l1);
            unsigned* p0 = (unsigned*)(smb + row*80 + cp*4);
            p0[0]                          = ((unsigned)__bfloat16_as_ushort(h1) << 16) | __bfloat16_as_ushort(h0);
            *(unsigned*)((char*)p0 + 25920)   = ((unsigned)__bfloat16_as_ushort(m1) << 16) | __bfloat16_as_ushort(m0);
            *(unsigned*)((char*)p0 + 2*25920) = ((unsigned)__bfloat16_as_ushort(l1) << 16) | __bfloat16_as_ushort(l0);
        }
    }
    __syncthreads();

    for (int step = 0; step < 9; step++) {
        if (step + 1 < 9) {
            const unsigned wdst = Xb + X1_BYTES + (unsigned)(((step+1) & 1) * W1_BYTES);
            const int ntap = step + 1;
            for (int j = tid; j < 768; j += 256) {
                int sb = j >> 8, rem = j & 255;
                const ull* src = g_w1f + ((long)(sb*9 + ntap)*2)*256 + rem*2;
                cpasync16(wdst + (unsigned)j*16, src);
            }
        }
        CP_COMMIT();
        CP_WAIT1();
        __syncthreads();
        mma_stepT<2>(smb, Xb, X1_BYTES, W1_BYTES, step & 1, step, wid, lane, xr, hs16, 25920, acc);
        __syncthreads();
    }

    float* sOut = (float*)Xs;   // [64 co][stride 68]
#pragma unroll
    for (int nt = 0; nt < 8; nt++) {
        const int co_l = nt*8 + (lane & 3)*2;
        const int co = co_l;
        const float s0c = g_scale[256 + co],     b0c = g_bias[256 + co];
        const float s1c = g_scale[256 + co + 1], b1c = g_bias[256 + co + 1];
        float q0 = fmaxf(fmaxf(fmaf(acc[0][nt][0], s0c, b0c), 0.f),
                         fmaxf(fmaf(acc[1][nt][0], s0c, b0c), 0.f));
        float q1 = fmaxf(fmaxf(fmaf(acc[0][nt][1], s1c, b1c), 0.f),
                         fmaxf(fmaf(acc[1][nt][1], s1c, b1c), 0.f));
        float q2 = fmaxf(fmaxf(fmaf(acc[0][nt][2], s0c, b0c), 0.f),
                         fmaxf(fmaf(acc[1][nt][2], s0c, b0c), 0.f));
        float q3 = fmaxf(fmaxf(fmaf(acc[0][nt][3], s1c, b1c), 0.f),
                         fmaxf(fmaf(acc[1][nt][3], s1c, b1c), 0.f));
        q0 = fmaxf(q0, __shfl_xor_sync(0xffffffffu, q0, 4));
        q1 = fmaxf(q1, __shfl_xor_sync(0xffffffffu, q1, 4));
        q2 = fmaxf(q2, __shfl_xor_sync(0xffffffffu, q2, 4));
        q3 = fmaxf(q3, __shfl_xor_sync(0xffffffffu, q3, 4));
        if (((lane >> 2) & 1) == 0) {
            const int px0 = (lane >> 2) >> 1;
            sOut[(co_l  )*68 + wid*8 + px0]     = q0;
            sOut[(co_l+1)*68 + wid*8 + px0]     = q1;
            sOut[(co_l  )*68 + wid*8 + px0 + 4] = q2;
            sOut[(co_l+1)*68 + wid*8 + px0 + 4] = q3;
        }
    }
    __syncthreads();
    {
        const int oy0 = ty0 >> 1, ox0 = tx0 >> 1;
        for (int i = tid; i < 64*64; i += 256) {
            int co = i >> 6, p = i & 63;
            int Y = p >> 3, X = p & 7;
            g_act1[((long)b*64 + co)*256 + (oy0 + Y)*16 + (ox0 + X)] = sOut[co*68 + p];
        }
    }
}

// ---------------- conv0 fp32 ----------------
__global__ __launch_bounds__(256, 2)
void conv0_kernel(const float* __restrict__ x, const float* __restrict__ wT)
{
    const int CIN = 3, COUT = 32, H = 32;
    const int b   = blockIdx.z;
    const int tyi = blockIdx.y / 2, txi = blockIdx.y % 2;
    const int ty0 = tyi * 16, tx0 = txi * 16;

    const int tid = threadIdx.x;
    const int cg  = tid >> 6;
    const int p   = tid & 63;
    const int py  = p >> 3, px = p & 7;
    const int oy  = 2*py,  ox = 2*px;

    extern __shared__ ull sIn2[];

    ull acc2[4][4];
#pragma unroll
    for (int i = 0; i < 4; i++)
#pragma unroll
        for (int k = 0; k < 4; k++) acc2[i][k] = 0ull;

    const int co0 = cg*8;

    const float* inb = x + (long)b*CIN*H*H;
    for (int i = tid; i < CIN*324; i += 256) {
        int c = i / 324; int r = i - c*324;
        int y = r / 18,  xx = r - y*18;
        int gy = ty0 + y - 1, gx = tx0 + xx - 1;
        float v = 0.f;
        if ((unsigned)gy < (unsigned)H && (unsigned)gx < (unsigned)H)
            v = inb[(long)c*H*H + gy*H + gx];
        sIn2[c*360 + y*20 + xx] = bcast2(v);
    }
    __syncthreads();

#pragma unroll
    for (int c = 0; c < CIN; c++) {
        const ull* sic = sIn2 + c*360 + oy*20 + ox;
        ull iv[4][4];
#pragma unroll
        for (int dy = 0; dy < 4; dy++) {
            ulonglong2 a0 = *(const ulonglong2*)(sic + dy*20);
            ulonglong2 a1 = *(const ulonglong2*)(sic + dy*20 + 2);
            iv[dy][0] = a0.x; iv[dy][1] = a0.y;
            iv[dy][2] = a1.x; iv[dy][3] = a1.y;
        }
        const float* wr = wT + (long)c*9*COUT + co0;
#pragma unroll
        for (int t = 0; t < 9; t++) {
            ulonglong2 w01 = __ldg((const ulonglong2*)(wr + t*COUT));
            ulonglong2 w23 = __ldg((const ulonglong2*)(wr + t*COUT + 4));
            const int dy = t / 3, dx = t % 3;
            ffma2(acc2[0][0], iv[dy  ][dx  ], w01.x);
            ffma2(acc2[0][1], iv[dy  ][dx  ], w01.y);
            ffma2(acc2[0][2], iv[dy  ][dx  ], w23.x);
            ffma2(acc2[0][3], iv[dy  ][dx  ], w23.y);
            ffma2(acc2[1][0], iv[dy  ][dx+1], w01.x);
            ffma2(acc2[1][1], iv[dy  ][dx+1], w01.y);
            ffma2(acc2[1][2], iv[dy  ][dx+1], w23.x);
            ffma2(acc2[1][3], iv[dy  ][dx+1], w23.y);
            ffma2(acc2[2][0], iv[dy+1][dx  ], w01.x);
            ffma2(acc2[2][1], iv[dy+1][dx  ], w01.y);
            ffma2(acc2[2][2], iv[dy+1][dx  ], w23.x);
            ffma2(acc2[2][3], iv[dy+1][dx  ], w23.y);
            ffma2(acc2[3][0], iv[dy+1][dx+1], w01.x);
            ffma2(acc2[3][1], iv[dy+1][dx+1], w01.y);
            ffma2(acc2[3][2], iv[dy+1][dx+1], w23.x);
            ffma2(acc2[3][3], iv[dy+1][dx+1], w23.y);
        }
    }

    float acc[4][8];
#pragma unroll
    for (int i = 0; i < 4; i++)
#pragma unroll
        for (int kk = 0; kk < 4; kk++)
            unpack2(acc[i][2*kk], acc[i][2*kk+1], acc2[i][kk]);

#pragma unroll
    for (int k = 0; k < 8; k++) {
        const float s  = g_scale[co0 + k];
        const float bi = g_bias [co0 + k];
#pragma unroll
        for (int r = 0; r < 2; r++)
#pragma unroll
            for (int s2 = 0; s2 < 2; s2++) {
                float v = fmaxf(fmaf(acc[r*2+s2][k], s, bi), 0.f);
                g_act0[(((long)b*32 + co0 + k)*H + (ty0+oy+r))*H + (tx0+ox+s2)] = v;
            }
    }
}

// ---------------- classifier + log_softmax + conf (+conf output) ------------
__global__ void classifier_kernel(const float* __restrict__ cls_w,
                                  const float* __restrict__ cls_b,
                                  float* __restrict__ out, int out_size)
{
    const int b = blockIdx.x;
    const int tid = threadIdx.x;   // 128
    __shared__ float sf[256];
    __shared__ float sl[80];
    for (int i = tid; i < 256; i += 128) sf[i] = g_feats[b*256 + i];
    __syncthreads();
    if (tid < 80) {
        const float* wr = cls_w + (long)tid * 256;
        float s = 0.f;
#pragma unroll 8
        for (int k = 0; k < 256; k++) s = fmaf(sf[k], wr[k], s);
        s += cls_b[tid];
        sl[tid] = s;
        g_logits[(long)b*80 + tid] = s;
    }
    __syncthreads();
    if (tid < 8) {
        float m = -1e30f;
        for (int c = 0; c < 10; c++) m = fmaxf(m, sl[tid*10 + c]);
        float se = 0.f;
        for (int c = 0; c < 10; c++) se += expf(sl[tid*10 + c] - m);
        float lse = m + logf(se);
        float cf = 0.f;
        for (int c = 0; c < 10; c++) {
            float lp = sl[tid*10 + c] - lse;
            cf += expf(lp) * lp;
        }
        g_conf[b*8 + tid] = cf;
        if (out_size >= 5120 + 4096)
            out[5120 + b*8 + tid] = cf;
    }
}

// ------- route (batched serial greedy) + fused final combine ---------------
__global__ __launch_bounds__(1024)
void route_final_kernel(float* __restrict__ out, int out_size)
{
    __shared__ unsigned long long keys[4096];
    __shared__ unsigned char D[4096];
    __shared__ unsigned char sc[512];
    __shared__ int ec_sh[8];

    const int tid = threadIdx.x;
    for (int i = tid; i < 4096; i += 1024) D[i] = 0;
    if (tid < 512) sc[tid] = 0;
    if (tid < 8)   ec_sh[tid] = 0;
    __syncthreads();

    ull ecpack = 0;   // thread 0's running expert counters (8x8 bits)
    int asg = 0;

    for (int cyc_i = 0; cyc_i < 4; cyc_i++) {
        for (int i = tid; i < 4096; i += 1024) {
            float v = g_conf[i];
            if (cyc_i > 0) v = v * (1.0f - (float)ec_sh[i & 7] / 160.0f);
            unsigned int fb = __float_as_uint(v);
            unsigned int ou = (fb & 0x80000000u) ? ~fb : (fb | 0x80000000u);
            keys[i] = ((unsigned long long)(~ou) << 32) | (unsigned int)i;
        }
        __syncthreads();
        for (int k2 = 2; k2 <= 4096; k2 <<= 1) {
            for (int j = k2 >> 1; j > 0; j >>= 1) {
                for (int i = tid; i < 4096; i += 1024) {
                    int ixj = i ^ j;
                    if (ixj > i) {
                        unsigned long long a = keys[i], bb = keys[ixj];
                        bool up = ((i & k2) == 0);
                        if ((a > bb) == up) { keys[i] = bb; keys[ixj] = a; }
                    }
                }
                __syncthreads();
            }
        }
        if (tid == 0) {
            int cyc = 0;
            for (int s0 = 0; s0 < 4096 && cyc < 256 && asg < 1024; s0 += 8) {
                int ids[8], Dv[8], scv[8], jb[8], bb[8];
#pragma unroll
                for (int k = 0; k < 8; k++)
                    ids[k] = (int)(keys[s0 + k] & 0xFFFFFFFFull);
#pragma unroll
                for (int k = 0; k < 8; k++) Dv[k] = D[ids[k]];
#pragma unroll
                for (int k = 0; k < 8; k++) { bb[k] = ids[k] >> 3; jb[k] = ids[k] & 7; }
#pragma unroll
                for (int k = 0; k < 8; k++) scv[k] = sc[bb[k]];
#pragma unroll
                for (int k = 0; k < 8; k++) {
                    if (cyc >= 256 || asg >= 1024) break;
                    int j = jb[k];
                    int ecv = (int)((ecpack >> (j*8)) & 0xFFull);
                    if (!Dv[k] && ecv < 160 && scv[k] < 2) {
                        D[ids[k]] = 1;
                        ecpack += 1ull << (j*8);
                        sc[bb[k]] = (unsigned char)(scv[k] + 1);
                        asg++; cyc++;
#pragma unroll
                        for (int q = k + 1; q < 8; q++)
                            if (bb[q] == bb[k]) scv[q]++;
                    }
                }
            }
            // publish ec for next cycle's key build
#pragma unroll
            for (int j = 0; j < 8; j++) ec_sh[j] = (int)((ecpack >> (j*8)) & 0xFFull);
        }
        __syncthreads();
    }

    // ---- fused final combine + D output ----
    for (int i = tid; i < 5120; i += 1024) {
        int b = i / 10, c = i - b*10;
        int nd = 0;
        float s = 0.f;
#pragma unroll
        for (int e = 0; e < 8; e++) {
            int d = D[b*8 + e];
            nd += d;
            if (d) s += g_conf[b*8 + e] * g_logits[(long)(b*8 + e)*10 + c];
        }
        out[i] = s / fmaxf((float)nd, 1.0f);
    }
    if (out_size >= 5120 + 8192) {
        for (int i = tid; i < 4096; i += 1024)
            out[5120 + 4096 + i] = D[i] ? 1.0f : 0.0f;
    }
}

// ---------------- launch ----------------
extern "C" void kernel_launch(void* const* d_in, const int* in_sizes, int n_in,
                              void* d_out, int out_size)
{
    const float* x = (const float*)d_in[0];
    FoldArgs fa;
    const float* w[4];
    for (int i = 0; i < 4; i++) {
        w [i]    = (const float*)d_in[1 + i*6 + 0];
        fa.cb[i] = (const float*)d_in[1 + i*6 + 1];
        fa.g [i] = (const float*)d_in[1 + i*6 + 2];
        fa.bt[i] = (const float*)d_in[1 + i*6 + 3];
        fa.rm[i] = (const float*)d_in[1 + i*6 + 4];
        fa.rv[i] = (const float*)d_in[1 + i*6 + 5];
    }
    const float* cls_w = (const float*)d_in[25];
    const float* cls_b = (const float*)d_in[26];

    const int SM3 = 3 * 360 * 8;
    cudaFuncSetAttribute(conv1_mma_kernel, cudaFuncAttributeMaxDynamicSharedMemorySize, SM_MMA1);
    cudaFuncSetAttribute(conv2_mma_kernel, cudaFuncAttributeMaxDynamicSharedMemorySize, SM_MMA1);
    cudaFuncSetAttribute(conv3_mma_kernel, cudaFuncAttributeMaxDynamicSharedMemorySize, SM_MMA1);

    fold_all_kernel<<<4, 256>>>(fa);

    float* wT0; unsigned* w3f; unsigned* w2f; unsigned* w1f;
    cudaGetSymbolAddress((void**)&wT0, g_wT0);
    cudaGetSymbolAddress((void**)&w3f, g_w3f);
    cudaGetSymbolAddress((void**)&w2f, g_w2f);
    cudaGetSymbolAddress((void**)&w1f, g_w1f);
    wt_kernel<<<(27*32 + 255)/256, 256>>>(w[0], wT0, 27, 32);
    w1frag_kernel<<<(27*2*8*32*2    + 255)/256, 256>>>(w[1], w1f);
    w2frag_kernel<<<(27*4*16*32*2   + 255)/256, 256>>>(w[2], w2f);
    w3frag_kernel<<<(27*2*4*32*32*2 + 255)/256, 256>>>(w[3], w3f);

    conv0_kernel<<<dim3(1,4,512), 256, SM3>>>(x, wT0);
    conv1_mma_kernel<<<2048, 256, SM_MMA1>>>();
    conv2_mma_kernel<<<1024, 256, SM_MMA1>>>();
    conv3_mma_kernel<<<2048, 256, SM_MMA1>>>();

    classifier_kernel<<<512, 128>>>(cls_w, cls_b, (float*)d_out, out_size);
    route_final_kernel<<<1, 1024>>>((float*)d_out, out_size);
}